// round 13
// baseline (speedup 1.0000x reference)
#include <cuda_runtime.h>
#include <cuda_fp16.h>
#include <math.h>
#include <stdint.h>

#define N_NODES 60000
#define N_EDGES 600000
#define N_GRAPH 512
#define DIM 128
#define N_LAYERS 3
#define GRID_G 8192
#define NB_SCAN 235      // ceil(60000/256)

// ---------------- device scratch ----------------
__device__ float g_H[(long long)N_NODES * 512];
__device__ __half g_Hn2[(long long)N_NODES * DIM];
__device__ __half g_Node2[(long long)N_NODES * DIM];
__device__ float g_bf[N_LAYERS * DIM];
__device__ float g_Spu[(long long)N_LAYERS * GRID_G * DIM];
__device__ __align__(256) __half g_TabP[(long long)N_LAYERS * GRID_G * DIM];
__device__ __align__(256) __half g_WbHi[9 * DIM * DIM];
__device__ __align__(256) __half g_WbLo[9 * DIM * DIM];
__device__ __align__(256) __half g_WfHi[N_LAYERS * DIM * DIM];
__device__ __align__(256) __half g_WfLo[N_LAYERS * DIM * DIM];
__device__ __align__(256) __half g_WrHi[64 * 512];
__device__ __align__(256) __half g_WrLo[64 * 512];
// CSR build
__device__ int g_cnt[N_NODES];
__device__ int g_off[N_NODES + 1];
__device__ int g_cur[N_NODES];
__device__ unsigned g_recP[N_EDGES];
// lookback scan state
__device__ volatile int g_flag[NB_SCAN];
__device__ volatile int g_aggrV[NB_SCAN];
__device__ volatile int g_inclV[NB_SCAN];

// ---------------- scalar helpers ----------------
__device__ __forceinline__ float sp_half(float x) {
    float bx = 0.5f * x;
    return bx > 14.0f ? x : 2.0f * log1pf(expf(bx));
}
__device__ __forceinline__ float sp_one(float x) {
    return x > 20.0f ? x : log1pf(expf(x));
}

// ---------------- HMMA fp16 ----------------
__device__ __forceinline__ void mma16816h(float* d, const uint32_t* a,
                                          uint32_t b0, uint32_t b1) {
    asm volatile(
        "mma.sync.aligned.m16n8k16.row.col.f32.f16.f16.f32 "
        "{%0,%1,%2,%3}, {%4,%5,%6,%7}, {%8,%9}, {%0,%1,%2,%3};"
        : "+f"(d[0]), "+f"(d[1]), "+f"(d[2]), "+f"(d[3])
        : "r"(a[0]), "r"(a[1]), "r"(a[2]), "r"(a[3]), "r"(b0), "r"(b1));
}

#define ASTR 68
#define A_WORDS (64 * ASTR)
#define B_WORDS (128 * ASTR)
#define BR_WORDS (64 * ASTR)
#define OFF_A 0
#define OFF_BHI  A_WORDS
#define OFF_BLO  (A_WORDS + B_WORDS)
#define OFF_BHI_R A_WORDS
#define OFF_BLO_R (A_WORDS + BR_WORDS)
#define TSMEM_M ((A_WORDS + 2 * B_WORDS) * 4)   // 87040
#define TSMEM_R ((A_WORDS + 2 * BR_WORDS) * 4)  // 52224

template<int NT>
__device__ __forceinline__ void mma_core2(const uint32_t* __restrict__ sm,
                                          int mw, int nwbase, int g, int tg,
                                          float acc[NT][4], int offBhi, int offBlo) {
    const uint32_t* A   = sm + OFF_A;
    const uint32_t* Bhi = sm + offBhi;
    const uint32_t* Blo = sm + offBlo;
    int ra0 = (mw * 16 + g) * ASTR;
    int ra1 = ra0 + 8 * ASTR;
    #pragma unroll
    for (int ks = 0; ks < 8; ks++) {
        int c = ks * 8 + tg;
        uint32_t ah[4];
        ah[0] = A[ra0 + c];     ah[1] = A[ra1 + c];
        ah[2] = A[ra0 + c + 4]; ah[3] = A[ra1 + c + 4];
        #pragma unroll
        for (int t = 0; t < NT; t++) {
            int rb = (nwbase + t * 8 + g) * ASTR;
            uint32_t bh0 = Bhi[rb + c], bh1 = Bhi[rb + c + 4];
            uint32_t bl0 = Blo[rb + c], bl1 = Blo[rb + c + 4];
            mma16816h(acc[t], ah, bh0, bh1);
            mma16816h(acc[t], ah, bl0, bl1);
        }
    }
}

__device__ __forceinline__ void load_A_f(uint32_t* sm, const float* __restrict__ X,
                                         int sx, int c0, int r0, int M, int tid) {
    uint32_t* A = sm + OFF_A;
    #pragma unroll
    for (int j = 0; j < 8; j++) {
        int f = tid + j * 256;
        int row = f >> 5, q = f & 31;
        float4 v = make_float4(0.f, 0.f, 0.f, 0.f);
        int gr = r0 + row;
        if (gr < M) v = *(const float4*)(X + (long long)gr * sx + c0 + q * 4);
        __half2 h01 = __floats2half2_rn(v.x, v.y);
        __half2 h23 = __floats2half2_rn(v.z, v.w);
        *(uint2*)(A + row * ASTR + q * 2) =
            make_uint2(*(uint32_t*)&h01, *(uint32_t*)&h23);
    }
}

__device__ __forceinline__ void load_A_h(uint32_t* sm, const __half* __restrict__ X,
                                         int r0, int M, int tid) {
    uint32_t* A = sm + OFF_A;
    #pragma unroll
    for (int j = 0; j < 4; j++) {
        int idx = tid + j * 256;
        int row = idx >> 4, q = idx & 15;
        uint4 v = make_uint4(0u, 0u, 0u, 0u);
        int gr = r0 + row;
        if (gr < M) v = *((const uint4*)(X + (long long)gr * DIM) + q);
        *(uint4*)(A + row * ASTR + q * 4) = v;
    }
}

__device__ __forceinline__ void load_B(uint32_t* sm, int offHi, int offLo,
                                       const __half* __restrict__ Whi,
                                       const __half* __restrict__ Wlo, int tid) {
    uint32_t* Bhi = sm + offHi;
    uint32_t* Blo = sm + offLo;
    const uint4* s1 = (const uint4*)Whi;
    const uint4* s2 = (const uint4*)Wlo;
    #pragma unroll
    for (int j = 0; j < 8; j++) {
        int i = tid + j * 256;
        int row = i >> 4, cq = (i & 15) * 4;
        *(uint4*)(Bhi + row * ASTR + cq) = s1[i];
        *(uint4*)(Blo + row * ASTR + cq) = s2[i];
    }
}

__device__ __forceinline__ void load_B_r(uint32_t* sm, const __half* __restrict__ Whi,
                                         const __half* __restrict__ Wlo,
                                         int chunk, int tid) {
    uint32_t* Bhi = sm + OFF_BHI_R;
    uint32_t* Blo = sm + OFF_BLO_R;
    const uint4* s1 = (const uint4*)Whi;
    const uint4* s2 = (const uint4*)Wlo;
    #pragma unroll
    for (int j = 0; j < 4; j++) {
        int i = tid + j * 256;
        int row = i >> 4, q = i & 15;
        int si = row * 64 + chunk * 16 + q;
        *(uint4*)(Bhi + row * ASTR + q * 4) = s1[si];
        *(uint4*)(Blo + row * ASTR + q * 4) = s2[si];
    }
}

// ---------------- setup1 ----------------
#define SB_SPU0  384
#define SB_PW0   3456
#define SB_PR0   3600
#define SB_ZC0   3632
#define SB_MS0   4101
#define SB_EMB0  4102
#define SB_TOTAL (4102 + 7500)

__global__ void setup1(const float* __restrict__ Wc2, const float* __restrict__ bc2,
                       const float* __restrict__ Wc3, const float* __restrict__ bc3,
                       const float* __restrict__ Wc1, const float* __restrict__ bc1,
                       const float* __restrict__ Wn1, const float* __restrict__ Wn2,
                       const float* __restrict__ Wn3, const float* __restrict__ Wr1,
                       const int* __restrict__ at, const float* __restrict__ emb,
                       float* __restrict__ out) {
    __shared__ float ssm[30 * DIM + DIM + 32];
    int b = blockIdx.x, tid = threadIdx.x;
    if (b < SB_SPU0) {
        int l = b >> 7, k = b & 127, j = tid;
        float* row = ssm;
        row[j] = Wc2[((long long)l * DIM + k) * DIM + j];
        __syncthreads();
        float acc = 0.0f;
        #pragma unroll 4
        for (int m = 0; m < DIM; m++)
            acc += row[m] * Wc3[((long long)l * DIM + m) * DIM + j];
        __half h = __float2half_rn(acc);
        __half lo = __float2half_rn(acc - __half2float(h));
        g_WfHi[(long long)l * DIM * DIM + j * DIM + k] = h;
        g_WfLo[(long long)l * DIM * DIM + j * DIM + k] = lo;
        if (k == 0) {
            float bacc = bc3[l * DIM + j];
            #pragma unroll 4
            for (int m = 0; m < DIM; m++)
                bacc += bc2[l * DIM + m] * Wc3[((long long)l * DIM + m) * DIM + j];
            g_bf[l * DIM + j] = bacc;
        }
    } else if (b < SB_PW0) {
        int idx = b - SB_SPU0;
        int x = idx & 1023, l = idx >> 10;
        float* wc = ssm;
        float* bc = ssm + 30 * DIM;
        float* rbf = ssm + 30 * DIM + DIM;
        const float* W = Wc1 + (long long)l * 30 * DIM;
        for (int i = tid; i < 30 * DIM; i += 128) wc[i] = W[i];
        bc[tid] = bc1[l * DIM + tid];
        __syncthreads();
        for (int gi = 0; gi < 8; gi++) {
            int g = x * 8 + gi;
            if (tid < 30) {
                float dg = (float)g * (10.0f / (float)(GRID_G - 1));
                float c = (float)tid * (10.0f / 29.0f);
                float dd = dg - c;
                rbf[tid] = expf(-dd * dd * 2.9f);
            }
            __syncthreads();
            float u = bc[tid];
            #pragma unroll
            for (int r = 0; r < 30; r++)
                u += rbf[r] * wc[r * DIM + tid];
            g_Spu[((long long)l * GRID_G + g) * DIM + tid] = sp_half(u);
            __syncthreads();
        }
    } else if (b < SB_PR0) {
        int idx = b - SB_PW0;
        int m = idx % 9, y = idx / 9;
        const float* src = (m < 3 ? Wn1 : (m < 6 ? Wn2 : Wn3)) + (long long)(m % 3) * DIM * DIM;
        __half* dh = g_WbHi + (long long)m * DIM * DIM;
        __half* dl = g_WbLo + (long long)m * DIM * DIM;
        int idx0 = y * 1024;
        #pragma unroll
        for (int i = 0; i < 8; i++) {
            int f = idx0 + i * 128 + tid;
            int k = f >> 7, n = f & 127;
            float v = src[f];
            __half h = __float2half_rn(v);
            __half l = __float2half_rn(v - __half2float(h));
            dh[n * DIM + k] = h;
            dl[n * DIM + k] = l;
        }
    } else if (b < SB_ZC0) {
        int idx = (b - SB_PR0) * 1024 + tid;
        #pragma unroll
        for (int i = 0; i < 8; i++) {
            int f = idx + i * 128;
            int k = f >> 6, n = f & 63;
            float v = Wr1[f];
            __half h = __float2half_rn(v);
            __half l = __float2half_rn(v - __half2float(h));
            g_WrHi[n * 512 + k] = h;
            g_WrLo[n * 512 + k] = l;
        }
    } else if (b < SB_MS0) {
        int i = (b - SB_ZC0) * 128 + tid;
        if (i < N_NODES) g_cnt[i] = 0;
    } else if (b < SB_EMB0) {
        #pragma unroll
        for (int i = 0; i < 4; i++) out[tid + i * 128] = 0.0f;
        g_flag[tid] = 0;
        if (tid < NB_SCAN - 128) g_flag[tid + 128] = 0;
    } else {
        int i0 = (b - SB_EMB0) * 256 + tid * 2;
        #pragma unroll
        for (int u = 0; u < 2; u++) {
            int i = i0 + u;
            int n = i >> 5, q = i & 31;
            float4 v = __ldg((const float4*)(emb + (long long)at[n] * DIM) + q);
            *(float4*)(g_H + (long long)n * 512 + q * 4) = v;
        }
    }
}

// ---------------- CSR: hist + lookback scan + scatter ----------------
__global__ void hist_kernel(const int* __restrict__ dst) {
    int e = blockIdx.x * 256 + threadIdx.x;
    if (e < N_EDGES) atomicAdd(&g_cnt[dst[e]], 1);
}

__global__ void scan_lb() {
    __shared__ int sh[256];
    __shared__ int s_excl;
    int b = blockIdx.x, tid = threadIdx.x;
    int n = b * 256 + tid;
    int v = (n < N_NODES) ? g_cnt[n] : 0;
    sh[tid] = v; __syncthreads();
    #pragma unroll
    for (int o = 1; o < 256; o <<= 1) {
        int t = (tid >= o) ? sh[tid - o] : 0;
        __syncthreads();
        sh[tid] += t;
        __syncthreads();
    }
    if (tid == 0) {
        int total = sh[255];
        if (b == 0) {
            g_inclV[0] = total;
            __threadfence();
            g_flag[0] = 2;
            s_excl = 0;
        } else {
            g_aggrV[b] = total;
            __threadfence();
            g_flag[b] = 1;
            int excl = 0, j = b - 1;
            while (true) {
                int f;
                do { f = g_flag[j]; } while (f == 0);
                if (f == 2) { excl += g_inclV[j]; break; }
                excl += g_aggrV[j];
                j--;
            }
            g_inclV[b] = excl + total;
            __threadfence();
            g_flag[b] = 2;
            s_excl = excl;
        }
    }
    __syncthreads();
    if (n < N_NODES) {
        int o = s_excl + sh[tid] - v;
        g_off[n] = o;
        g_cur[n] = o;
    }
    if (n == 0) g_off[N_NODES] = N_EDGES;
}

__global__ void scatter_kernel(const int* __restrict__ src, const int* __restrict__ dst,
                               const float* __restrict__ dist) {
    int e = blockIdx.x * 256 + threadIdx.x;
    if (e >= N_EDGES) return;
    int d = __ldg(dst + e);
    int pos = atomicAdd(&g_cur[d], 1);
    float di = __ldg(dist + e);
    float t = di * ((float)(GRID_G - 1) / 10.0f);
    int gg = (int)(t + 0.5f);
    gg = gg < GRID_G - 1 ? gg : GRID_G - 1;
    g_recP[pos] = (unsigned)__ldg(src + e) | ((unsigned)gg << 16);
}

// ---------------- paired-edge gather: 2 edges per warp step, uint4 lanes ----------------
__device__ __forceinline__ void acc8(float* a, uint4 tv, uint4 hv) {
    const __half2* t = (const __half2*)&tv;
    const __half2* h = (const __half2*)&hv;
    #pragma unroll
    for (int k = 0; k < 4; k++) {
        float2 tf = __half22float2(t[k]);
        float2 hf = __half22float2(h[k]);
        a[2 * k]     = fmaf(tf.x, hf.x, a[2 * k]);
        a[2 * k + 1] = fmaf(tf.y, hf.y, a[2 * k + 1]);
    }
}

__global__ __launch_bounds__(256) void edge_gather(
    const __half* __restrict__ tabp,
    const __half* __restrict__ hn,
    __half* __restrict__ node2)
{
    int wid = threadIdx.x >> 5, lane = threadIdx.x & 31;
    int n = blockIdx.x * 8 + wid;
    if (n >= N_NODES) return;
    int q = lane & 15;          // feature quarter: halves [8q, 8q+8)
    int half = lane >> 4;       // which edge of the pair
    int beg = __ldg(&g_off[n]);
    int end = __ldg(&g_off[n + 1]);
    float acc[8];
    #pragma unroll
    for (int k = 0; k < 8; k++) acc[k] = 0.0f;

    int i = beg;
    for (; i + 4 <= end; i += 4) {
        unsigned ra = __ldg(&g_recP[i + half]);
        unsigned rb = __ldg(&g_recP[i + 2 + half]);
        uint4 ta = __ldg((const uint4*)(tabp + (long long)(ra >> 16) * DIM) + q);
        uint4 tb = __ldg((const uint4*)(tabp + (long long)(rb >> 16) * DIM) + q);
        uint4 ha = __ldg((const uint4*)(hn + (long long)(ra & 0xFFFFu) * DIM) + q);
        uint4 hb = __ldg((const uint4*)(hn + (long long)(rb & 0xFFFFu) * DIM) + q);
        acc8(acc, ta, ha);
        acc8(acc, tb, hb);
    }
    for (; i + 2 <= end; i += 2) {
        unsigned r = __ldg(&g_recP[i + half]);
        uint4 tv = __ldg((const uint4*)(tabp + (long long)(r >> 16) * DIM) + q);
        uint4 hv = __ldg((const uint4*)(hn + (long long)(r & 0xFFFFu) * DIM) + q);
        acc8(acc, tv, hv);
    }
    if (i < end && half == 0) {
        unsigned r = __ldg(&g_recP[i]);
        uint4 tv = __ldg((const uint4*)(tabp + (long long)(r >> 16) * DIM) + q);
        uint4 hv = __ldg((const uint4*)(hn + (long long)(r & 0xFFFFu) * DIM) + q);
        acc8(acc, tv, hv);
    }
    // combine the two halves
    #pragma unroll
    for (int k = 0; k < 8; k++)
        acc[k] += __shfl_down_sync(0xffffffffu, acc[k], 16);
    if (half == 0) {
        __half2 o0 = __floats2half2_rn(acc[0], acc[1]);
        __half2 o1 = __floats2half2_rn(acc[2], acc[3]);
        __half2 o2 = __floats2half2_rn(acc[4], acc[5]);
        __half2 o3 = __floats2half2_rn(acc[6], acc[7]);
        uint4 o = make_uint4(*(uint32_t*)&o0, *(uint32_t*)&o1,
                             *(uint32_t*)&o2, *(uint32_t*)&o3);
        *((uint4*)(node2 + (long long)n * DIM) + q) = o;
    }
}

// ---------------- merged: gemm_tab (384 blocks) + gemm_m1 (938 blocks) ----------------
__global__ __launch_bounds__(256) void gemm_tab_m1(
    const float* __restrict__ b_n1, int M)
{
    extern __shared__ uint32_t sm[];
    int tid = threadIdx.x, wid = tid >> 5, lane = tid & 31;
    int mw = wid & 3, nw = wid >> 2;
    int g = lane >> 2, tg = lane & 3;

    if (blockIdx.x < 384) {
        int l = blockIdx.x / 128;
        int r0 = (blockIdx.x % 128) * 64;
        const float* X = g_Spu + (long long)l * GRID_G * DIM;
        __half* Y = g_TabP + (long long)l * GRID_G * DIM;

        load_A_f(sm, X, DIM, 0, r0, GRID_G, tid);
        load_B(sm, OFF_BHI, OFF_BLO,
               g_WfHi + (long long)l * DIM * DIM, g_WfLo + (long long)l * DIM * DIM, tid);
        __syncthreads();

        float acc[8][4];
        #pragma unroll
        for (int t = 0; t < 8; t++)
            #pragma unroll
            for (int i = 0; i < 4; i++) acc[t][i] = 0.0f;
        mma_core2<8>(sm, mw, nw * 64, g, tg, acc, OFF_BHI, OFF_BLO);

        int row0 = r0 + mw * 16 + g, row1 = row0 + 8;
        #pragma unroll
        for (int t = 0; t < 8; t++) {
            int col = nw * 64 + t * 8 + tg * 2;
            float b0 = g_bf[l * DIM + col], b1 = g_bf[l * DIM + col + 1];
            *(__half2*)(Y + (long long)row0 * DIM + col) =
                __floats2half2_rn(acc[t][0] + b0, acc[t][1] + b1);
            *(__half2*)(Y + (long long)row1 * DIM + col) =
                __floats2half2_rn(acc[t][2] + b0, acc[t][3] + b1);
        }
    } else {
        int r0 = (int)(blockIdx.x - 384) * 64;

        load_A_f(sm, g_H, 512, 0, r0, M, tid);
        load_B(sm, OFF_BHI, OFF_BLO, g_WbHi, g_WbLo, tid);
        __syncthreads();

        float acc[8][4];
        #pragma unroll
        for (int t = 0; t < 8; t++)
            #pragma unroll
            for (int i = 0; i < 4; i++) acc[t][i] = 0.0f;
        mma_core2<8>(sm, mw, nw * 64, g, tg, acc, OFF_BHI, OFF_BLO);

        int row0 = r0 + mw * 16 + g, row1 = row0 + 8;
        #pragma unroll
        for (int t = 0; t < 8; t++) {
            int col = nw * 64 + t * 8 + tg * 2;
            float b0 = __ldg(b_n1 + col) + 1.0f;
            float b1 = __ldg(b_n1 + col + 1) + 1.0f;
            if (row0 < M)
                *(__half2*)(g_Hn2 + (long long)row0 * DIM + col) =
                    __floats2half2_rn(acc[t][0] + b0, acc[t][1] + b1);
            if (row1 < M)
                *(__half2*)(g_Hn2 + (long long)row1 * DIM + col) =
                    __floats2half2_rn(acc[t][2] + b0, acc[t][3] + b1);
        }
    }
}

// ---------------- fused: H' = H + sp(Node2@W2+b2)@W3+b3 ; optionally next Hn ----------------
__global__ __launch_bounds__(256) void gemm_m23(
    const __half* __restrict__ X,
    const __half* __restrict__ W2hi, const __half* __restrict__ W2lo,
    const float* __restrict__ b2,
    const __half* __restrict__ W3hi, const __half* __restrict__ W3lo,
    const float* __restrict__ b3,
    const float* __restrict__ Res, int sr,
    float* __restrict__ Y, int sy,
    const __half* __restrict__ W1hi, const __half* __restrict__ W1lo,
    const float* __restrict__ b1n,
    __half* __restrict__ Hn2,
    int has_next, int M)
{
    extern __shared__ uint32_t sm[];
    uint32_t* A = sm + OFF_A;
    int tid = threadIdx.x, wid = tid >> 5, lane = tid & 31;
    int mw = wid & 3, nw = wid >> 2;
    int g = lane >> 2, tg = lane & 3;
    int r0 = blockIdx.x * 64;
    int rl0 = mw * 16 + g, rl1 = rl0 + 8;
    int row0 = r0 + rl0, row1 = row0 + 8;

    load_A_h(sm, X, r0, M, tid);
    load_B(sm, OFF_BHI, OFF_BLO, W2hi, W2lo, tid);
    __syncthreads();

    float acc[8][4];
    #pragma unroll
    for (int t = 0; t < 8; t++)
        #pragma unroll
        for (int i = 0; i < 4; i++) acc[t][i] = 0.0f;
    mma_core2<8>(sm, mw, nw * 64, g, tg, acc, OFF_BHI, OFF_BLO);

    #pragma unroll
    for (int t = 0; t < 8; t++) {
        int col = nw * 64 + t * 8 + tg * 2;
        float b0 = __ldg(b2 + col), b1 = __ldg(b2 + col + 1);
        __half2 v0 = __floats2half2_rn(sp_half(acc[t][0] + b0), sp_half(acc[t][1] + b1));
        __half2 v1 = __floats2half2_rn(sp_half(acc[t][2] + b0), sp_half(acc[t][3] + b1));
        A[rl0 * ASTR + (col >> 1)] = *(uint32_t*)&v0;
        A[rl1 * ASTR + (col >> 1)] = *(uint32_t*)&v1;
    }
    __syncthreads();
    load_B(sm, OFF_BHI, OFF_BLO, W3hi, W3lo, tid);
    __syncthreads();

    #pragma unroll
    for (int t = 0; t < 8; t++)
        #pragma unroll
        for (int i = 0; i < 4; i++) acc[t][i] = 0.0f;
    mma_core2<8>(sm, mw, nw * 64, g, tg, acc, OFF_BHI, OFF_BLO);

    #pragma unroll
    for (int t = 0; t < 8; t++) {
        int col = nw * 64 + t * 8 + tg * 2;
        float b0 = __ldg(b3 + col), b1 = __ldg(b3 + col + 1);
        float y0 = acc[t][0] + b0, y1 = acc[t][1] + b1;
        float y2 = acc[t][2] + b0, y3 = acc[t][3] + b1;
        if (row0 < M) {
            float2 r = *(const float2*)(Res + (long long)row0 * sr + col);
            y0 += r.x; y1 += r.y;
            *(float2*)(Y + (long long)row0 * sy + col) = make_float2(y0, y1);
        }
        if (row1 < M) {
            float2 r = *(const float2*)(Res + (long long)row1 * sr + col);
            y2 += r.x; y3 += r.y;
            *(float2*)(Y + (long long)row1 * sy + col) = make_float2(y2, y3);
        }
        if (has_next) {
            __half2 v0 = __floats2half2_rn(y0, y1);
            __half2 v1 = __floats2half2_rn(y2, y3);
            A[rl0 * ASTR + (col >> 1)] = *(uint32_t*)&v0;
            A[rl1 * ASTR + (col >> 1)] = *(uint32_t*)&v1;
        }
    }
    if (!has_next) return;

    __syncthreads();
    load_B(sm, OFF_BHI, OFF_BLO, W1hi, W1lo, tid);
    __syncthreads();

    #pragma unroll
    for (int t = 0; t < 8; t++)
        #pragma unroll
        for (int i = 0; i < 4; i++) acc[t][i] = 0.0f;
    mma_core2<8>(sm, mw, nw * 64, g, tg, acc, OFF_BHI, OFF_BLO);

    #pragma unroll
    for (int t = 0; t < 8; t++) {
        int col = nw * 64 + t * 8 + tg * 2;
        float b0 = __ldg(b1n + col) + 1.0f;
        float b1 = __ldg(b1n + col + 1) + 1.0f;
        if (row0 < M)
            *(__half2*)(Hn2 + (long long)row0 * DIM + col) =
                __floats2half2_rn(acc[t][0] + b0, acc[t][1] + b1);
        if (row1 < M)
            *(__half2*)(Hn2 + (long long)row1 * DIM + col) =
                __floats2half2_rn(acc[t][2] + b0, acc[t][3] + b1);
    }
}

// ---------------- fused readout ----------------
__global__ __launch_bounds__(256) void gemm_r(
    const float* __restrict__ X,
    const __half* __restrict__ Whi, const __half* __restrict__ Wlo,
    const float* __restrict__ br1, const float* __restrict__ Wr2,
    const float* __restrict__ br2,
    const int* __restrict__ gid, float* __restrict__ out, int M)
{
    extern __shared__ uint32_t sm[];
    __shared__ float res[64];
    int tid = threadIdx.x, wid = tid >> 5, lane = tid & 31;
    int mw = wid & 3, nw = wid >> 2;
    int g = lane >> 2, tg = lane & 3;
    int r0 = blockIdx.x * 64;
    if (tid < 64) res[tid] = 0.0f;

    float acc[4][4];
    #pragma unroll
    for (int t = 0; t < 4; t++)
        #pragma unroll
        for (int i = 0; i < 4; i++) acc[t][i] = 0.0f;

    for (int ch = 0; ch < 4; ch++) {
        load_A_f(sm, X, 512, ch * 128, r0, M, tid);
        load_B_r(sm, Whi, Wlo, ch, tid);
        __syncthreads();
        mma_core2<4>(sm, mw, nw * 32, g, tg, acc, OFF_BHI_R, OFF_BLO_R);
        __syncthreads();
    }

    float p0 = 0.0f, p1 = 0.0f;
    #pragma unroll
    for (int t = 0; t < 4; t++) {
        int col = nw * 32 + t * 8 + tg * 2;
        float b0 = __ldg(br1 + col), b1 = __ldg(br1 + col + 1);
        float w0 = __ldg(Wr2 + col), w1 = __ldg(Wr2 + col + 1);
        p0 += sp_one(acc[t][0] + b0) * w0 + sp_one(acc[t][1] + b1) * w1;
        p1 += sp_one(acc[t][2] + b0) * w0 + sp_one(acc[t][3] + b1) * w1;
    }
    p0 += __shfl_down_sync(0xffffffff, p0, 1);
    p0 += __shfl_down_sync(0xffffffff, p0, 2);
    p1 += __shfl_down_sync(0xffffffff, p1, 1);
    p1 += __shfl_down_sync(0xffffffff, p1, 2);
    if (tg == 0) {
        atomicAdd(&res[mw * 16 + g], p0);
        atomicAdd(&res[mw * 16 + g + 8], p1);
    }
    __syncthreads();
    if (tid < 64) {
        int row = r0 + tid;
        if (row < M) atomicAdd(out + __ldg(gid + row), res[tid] + __ldg(br2));
    }
}

// ---------------- launch ----------------
extern "C" void kernel_launch(void* const* d_in, const int* in_sizes, int n_in,
                              void* d_out, int out_size) {
    const int*   atom_type = (const int*)d_in[0];
    const int*   src  = (const int*)d_in[1];
    const int*   dst  = (const int*)d_in[2];
    const int*   gid  = (const int*)d_in[3];
    const float* dist = (const float*)d_in[4];
    const float* emb  = (const float*)d_in[5];
    const float* W_n1 = (const float*)d_in[6];  const float* b_n1 = (const float*)d_in[7];
    const float* W_c1 = (const float*)d_in[8];  const float* b_c1 = (const float*)d_in[9];
    const float* W_c2 = (const float*)d_in[10]; const float* b_c2 = (const float*)d_in[11];
    const float* W_c3 = (const float*)d_in[12]; const float* b_c3 = (const float*)d_in[13];
    const float* W_n2 = (const float*)d_in[14]; const float* b_n2 = (const float*)d_in[15];
    const float* W_n3 = (const float*)d_in[16]; const float* b_n3 = (const float*)d_in[17];
    const float* W_r1 = (const float*)d_in[18]; const float* b_r1 = (const float*)d_in[19];
    const float* W_r2 = (const float*)d_in[20]; const float* b_r2 = (const float*)d_in[21];
    float* out = (float*)d_out;

    float* H;
    __half *Hn2, *Node2, *TabP;
    __half *WbHi, *WbLo, *WrHi, *WrLo;
    cudaGetSymbolAddress((void**)&H,     g_H);
    cudaGetSymbolAddress((void**)&Hn2,   g_Hn2);
    cudaGetSymbolAddress((void**)&Node2, g_Node2);
    cudaGetSymbolAddress((void**)&TabP,  g_TabP);
    cudaGetSymbolAddress((void**)&WbHi,  g_WbHi);
    cudaGetSymbolAddress((void**)&WbLo,  g_WbLo);
    cudaGetSymbolAddress((void**)&WrHi,  g_WrHi);
    cudaGetSymbolAddress((void**)&WrLo,  g_WrLo);

    cudaFuncSetAttribute(gemm_tab_m1, cudaFuncAttributeMaxDynamicSharedMemorySize, TSMEM_M);
    cudaFuncSetAttribute(gemm_m23,    cudaFuncAttributeMaxDynamicSharedMemorySize, TSMEM_M);
    cudaFuncSetAttribute(gemm_r,      cudaFuncAttributeMaxDynamicSharedMemorySize, TSMEM_R);

    // one-time stream/event resources (host-side only; identical captured work each call)
    static cudaStream_t s2 = nullptr;
    static cudaEvent_t evA = nullptr, evB = nullptr;
    if (!s2) {
        cudaStreamCreateWithFlags(&s2, cudaStreamNonBlocking);
        cudaEventCreateWithFlags(&evA, cudaEventDisableTiming);
        cudaEventCreateWithFlags(&evB, cudaEventDisableTiming);
    }

    const int M = N_NODES;
    const int GB64 = (M + 63) / 64;     // 938
    const int EB = (N_EDGES + 255) / 256;

    // 1) all independent setup work
    setup1<<<SB_TOTAL, 128>>>(W_c2, b_c2, W_c3, b_c3, W_c1, b_c1,
                              W_n1, W_n2, W_n3, W_r1, atom_type, emb, out);
    // fork CSR chain onto s2, concurrent with gemm_tab_m1 below
    cudaEventRecord(evA, 0);
    cudaStreamWaitEvent(s2, evA, 0);
    hist_kernel<<<EB, 256, 0, s2>>>(dst);
    scan_lb<<<NB_SCAN, 256, 0, s2>>>();
    scatter_kernel<<<EB, 256, 0, s2>>>(src, dst, dist);
    cudaEventRecord(evB, s2);
    // main stream: table GEMM + layer-0 h_new
    gemm_tab_m1<<<384 + GB64, 256, TSMEM_M>>>(b_n1, M);
    // join before first gather (needs recP/off)
    cudaStreamWaitEvent(0, evB, 0);

    for (int l = 0; l < N_LAYERS; l++) {
        edge_gather<<<(N_NODES + 7) / 8, 256>>>(
            TabP + (long long)l * GRID_G * DIM, Hn2, Node2);
        int nl = l + 1;
        int has_next = (nl < N_LAYERS);
        gemm_m23<<<GB64, 256, TSMEM_M>>>(
            Node2,
            WbHi + (long long)(3 + l) * DIM * DIM, WbLo + (long long)(3 + l) * DIM * DIM,
            b_n2 + l * 128,
            WbHi + (long long)(6 + l) * DIM * DIM, WbLo + (long long)(6 + l) * DIM * DIM,
            b_n3 + l * 128,
            H + l * 128, 512, H + nl * 128, 512,
            WbHi + (long long)(has_next ? nl : 0) * DIM * DIM,
            WbLo + (long long)(has_next ? nl : 0) * DIM * DIM,
            b_n1 + (has_next ? nl : 0) * 128,
            Hn2, has_next, M);
    }

    gemm_r<<<GB64, 256, TSMEM_R>>>(H, WrHi, WrLo, b_r1, W_r2, b_r2, gid, out, M);
}

// round 14
// speedup vs baseline: 1.4418x; 1.4418x over previous
#include <cuda_runtime.h>
#include <cuda_fp16.h>
#include <math.h>
#include <stdint.h>

#define N_NODES 60000
#define N_EDGES 600000
#define N_GRAPH 512
#define DIM 128
#define N_LAYERS 3
#define GRID_G 8192
#define NB_SCAN 235      // ceil(60000/256)

// ---------------- device scratch ----------------
__device__ float g_H[(long long)N_NODES * 512];
__device__ __half g_Hn2[(long long)N_NODES * DIM];
__device__ __half g_Node2[(long long)N_NODES * DIM];
__device__ float g_bf[N_LAYERS * DIM];
__device__ float g_Spu[(long long)N_LAYERS * GRID_G * DIM];
__device__ __align__(256) __half g_TabP[(long long)N_LAYERS * GRID_G * DIM];
__device__ __align__(256) __half g_WbHi[9 * DIM * DIM];
__device__ __align__(256) __half g_WbLo[9 * DIM * DIM];
__device__ __align__(256) __half g_WfHi[N_LAYERS * DIM * DIM];
__device__ __align__(256) __half g_WfLo[N_LAYERS * DIM * DIM];
__device__ __align__(256) __half g_WrHi[64 * 512];
__device__ __align__(256) __half g_WrLo[64 * 512];
// CSR build
__device__ int g_cnt[N_NODES];
__device__ int g_off[N_NODES + 1];
__device__ int g_cur[N_NODES];
__device__ __align__(16) unsigned g_recP[N_EDGES + 4];
// lookback scan state
__device__ volatile int g_flag[NB_SCAN];
__device__ volatile int g_aggrV[NB_SCAN];
__device__ volatile int g_inclV[NB_SCAN];

// ---------------- scalar helpers ----------------
__device__ __forceinline__ float sp_half(float x) {
    float bx = 0.5f * x;
    return bx > 14.0f ? x : 2.0f * log1pf(expf(bx));
}
__device__ __forceinline__ float sp_one(float x) {
    return x > 20.0f ? x : log1pf(expf(x));
}

// ---------------- HMMA fp16 ----------------
__device__ __forceinline__ void mma16816h(float* d, const uint32_t* a,
                                          uint32_t b0, uint32_t b1) {
    asm volatile(
        "mma.sync.aligned.m16n8k16.row.col.f32.f16.f16.f32 "
        "{%0,%1,%2,%3}, {%4,%5,%6,%7}, {%8,%9}, {%0,%1,%2,%3};"
        : "+f"(d[0]), "+f"(d[1]), "+f"(d[2]), "+f"(d[3])
        : "r"(a[0]), "r"(a[1]), "r"(a[2]), "r"(a[3]), "r"(b0), "r"(b1));
}

#define ASTR 68
#define A_WORDS (64 * ASTR)
#define B_WORDS (128 * ASTR)
#define BR_WORDS (64 * ASTR)
#define OFF_A 0
#define OFF_BHI  A_WORDS
#define OFF_BLO  (A_WORDS + B_WORDS)
#define OFF_BHI_R A_WORDS
#define OFF_BLO_R (A_WORDS + BR_WORDS)
#define TSMEM_M ((A_WORDS + 2 * B_WORDS) * 4)   // 87040
#define TSMEM_R ((A_WORDS + 2 * BR_WORDS) * 4)  // 52224

template<int NT>
__device__ __forceinline__ void mma_core2(const uint32_t* __restrict__ sm,
                                          int mw, int nwbase, int g, int tg,
                                          float acc[NT][4], int offBhi, int offBlo) {
    const uint32_t* A   = sm + OFF_A;
    const uint32_t* Bhi = sm + offBhi;
    const uint32_t* Blo = sm + offBlo;
    int ra0 = (mw * 16 + g) * ASTR;
    int ra1 = ra0 + 8 * ASTR;
    #pragma unroll
    for (int ks = 0; ks < 8; ks++) {
        int c = ks * 8 + tg;
        uint32_t ah[4];
        ah[0] = A[ra0 + c];     ah[1] = A[ra1 + c];
        ah[2] = A[ra0 + c + 4]; ah[3] = A[ra1 + c + 4];
        #pragma unroll
        for (int t = 0; t < NT; t++) {
            int rb = (nwbase + t * 8 + g) * ASTR;
            uint32_t bh0 = Bhi[rb + c], bh1 = Bhi[rb + c + 4];
            uint32_t bl0 = Blo[rb + c], bl1 = Blo[rb + c + 4];
            mma16816h(acc[t], ah, bh0, bh1);
            mma16816h(acc[t], ah, bl0, bl1);
        }
    }
}

__device__ __forceinline__ void load_A_f(uint32_t* sm, const float* __restrict__ X,
                                         int sx, int c0, int r0, int M, int tid) {
    uint32_t* A = sm + OFF_A;
    #pragma unroll
    for (int j = 0; j < 8; j++) {
        int f = tid + j * 256;
        int row = f >> 5, q = f & 31;
        float4 v = make_float4(0.f, 0.f, 0.f, 0.f);
        int gr = r0 + row;
        if (gr < M) v = *(const float4*)(X + (long long)gr * sx + c0 + q * 4);
        __half2 h01 = __floats2half2_rn(v.x, v.y);
        __half2 h23 = __floats2half2_rn(v.z, v.w);
        *(uint2*)(A + row * ASTR + q * 2) =
            make_uint2(*(uint32_t*)&h01, *(uint32_t*)&h23);
    }
}

__device__ __forceinline__ void load_A_h(uint32_t* sm, const __half* __restrict__ X,
                                         int r0, int M, int tid) {
    uint32_t* A = sm + OFF_A;
    #pragma unroll
    for (int j = 0; j < 4; j++) {
        int idx = tid + j * 256;
        int row = idx >> 4, q = idx & 15;
        uint4 v = make_uint4(0u, 0u, 0u, 0u);
        int gr = r0 + row;
        if (gr < M) v = *((const uint4*)(X + (long long)gr * DIM) + q);
        *(uint4*)(A + row * ASTR + q * 4) = v;
    }
}

__device__ __forceinline__ void load_B(uint32_t* sm, int offHi, int offLo,
                                       const __half* __restrict__ Whi,
                                       const __half* __restrict__ Wlo, int tid) {
    uint32_t* Bhi = sm + offHi;
    uint32_t* Blo = sm + offLo;
    const uint4* s1 = (const uint4*)Whi;
    const uint4* s2 = (const uint4*)Wlo;
    #pragma unroll
    for (int j = 0; j < 8; j++) {
        int i = tid + j * 256;
        int row = i >> 4, cq = (i & 15) * 4;
        *(uint4*)(Bhi + row * ASTR + cq) = s1[i];
        *(uint4*)(Blo + row * ASTR + cq) = s2[i];
    }
}

__device__ __forceinline__ void load_B_r(uint32_t* sm, const __half* __restrict__ Whi,
                                         const __half* __restrict__ Wlo,
                                         int chunk, int tid) {
    uint32_t* Bhi = sm + OFF_BHI_R;
    uint32_t* Blo = sm + OFF_BLO_R;
    const uint4* s1 = (const uint4*)Whi;
    const uint4* s2 = (const uint4*)Wlo;
    #pragma unroll
    for (int j = 0; j < 4; j++) {
        int i = tid + j * 256;
        int row = i >> 4, q = i & 15;
        int si = row * 64 + chunk * 16 + q;
        *(uint4*)(Bhi + row * ASTR + q * 4) = s1[si];
        *(uint4*)(Blo + row * ASTR + q * 4) = s2[si];
    }
}

// ---------------- setup1 ----------------
#define SB_SPU0  384
#define SB_PW0   3456
#define SB_PR0   3600
#define SB_ZC0   3632
#define SB_MS0   4101
#define SB_EMB0  4102
#define SB_TOTAL (4102 + 7500)

__global__ void setup1(const float* __restrict__ Wc2, const float* __restrict__ bc2,
                       const float* __restrict__ Wc3, const float* __restrict__ bc3,
                       const float* __restrict__ Wc1, const float* __restrict__ bc1,
                       const float* __restrict__ Wn1, const float* __restrict__ Wn2,
                       const float* __restrict__ Wn3, const float* __restrict__ Wr1,
                       const int* __restrict__ at, const float* __restrict__ emb,
                       float* __restrict__ out) {
    __shared__ float ssm[30 * DIM + DIM + 32];
    int b = blockIdx.x, tid = threadIdx.x;
    if (b < SB_SPU0) {
        int l = b >> 7, k = b & 127, j = tid;
        float* row = ssm;
        row[j] = Wc2[((long long)l * DIM + k) * DIM + j];
        __syncthreads();
        float acc = 0.0f;
        #pragma unroll 4
        for (int m = 0; m < DIM; m++)
            acc += row[m] * Wc3[((long long)l * DIM + m) * DIM + j];
        __half h = __float2half_rn(acc);
        __half lo = __float2half_rn(acc - __half2float(h));
        g_WfHi[(long long)l * DIM * DIM + j * DIM + k] = h;
        g_WfLo[(long long)l * DIM * DIM + j * DIM + k] = lo;
        if (k == 0) {
            float bacc = bc3[l * DIM + j];
            #pragma unroll 4
            for (int m = 0; m < DIM; m++)
                bacc += bc2[l * DIM + m] * Wc3[((long long)l * DIM + m) * DIM + j];
            g_bf[l * DIM + j] = bacc;
        }
    } else if (b < SB_PW0) {
        int idx = b - SB_SPU0;
        int x = idx & 1023, l = idx >> 10;
        float* wc = ssm;
        float* bc = ssm + 30 * DIM;
        float* rbf = ssm + 30 * DIM + DIM;
        const float* W = Wc1 + (long long)l * 30 * DIM;
        for (int i = tid; i < 30 * DIM; i += 128) wc[i] = W[i];
        bc[tid] = bc1[l * DIM + tid];
        __syncthreads();
        for (int gi = 0; gi < 8; gi++) {
            int g = x * 8 + gi;
            if (tid < 30) {
                float dg = (float)g * (10.0f / (float)(GRID_G - 1));
                float c = (float)tid * (10.0f / 29.0f);
                float dd = dg - c;
                rbf[tid] = expf(-dd * dd * 2.9f);
            }
            __syncthreads();
            float u = bc[tid];
            #pragma unroll
            for (int r = 0; r < 30; r++)
                u += rbf[r] * wc[r * DIM + tid];
            g_Spu[((long long)l * GRID_G + g) * DIM + tid] = sp_half(u);
            __syncthreads();
        }
    } else if (b < SB_PR0) {
        int idx = b - SB_PW0;
        int m = idx % 9, y = idx / 9;
        const float* src = (m < 3 ? Wn1 : (m < 6 ? Wn2 : Wn3)) + (long long)(m % 3) * DIM * DIM;
        __half* dh = g_WbHi + (long long)m * DIM * DIM;
        __half* dl = g_WbLo + (long long)m * DIM * DIM;
        int idx0 = y * 1024;
        #pragma unroll
        for (int i = 0; i < 8; i++) {
            int f = idx0 + i * 128 + tid;
            int k = f >> 7, n = f & 127;
            float v = src[f];
            __half h = __float2half_rn(v);
            __half l = __float2half_rn(v - __half2float(h));
            dh[n * DIM + k] = h;
            dl[n * DIM + k] = l;
        }
    } else if (b < SB_ZC0) {
        int idx = (b - SB_PR0) * 1024 + tid;
        #pragma unroll
        for (int i = 0; i < 8; i++) {
            int f = idx + i * 128;
            int k = f >> 6, n = f & 63;
            float v = Wr1[f];
            __half h = __float2half_rn(v);
            __half l = __float2half_rn(v - __half2float(h));
            g_WrHi[n * 512 + k] = h;
            g_WrLo[n * 512 + k] = l;
        }
    } else if (b < SB_MS0) {
        int i = (b - SB_ZC0) * 128 + tid;
        if (i < N_NODES) g_cnt[i] = 0;
    } else if (b < SB_EMB0) {
        #pragma unroll
        for (int i = 0; i < 4; i++) out[tid + i * 128] = 0.0f;
        g_flag[tid] = 0;
        if (tid < NB_SCAN - 128) g_flag[tid + 128] = 0;
    } else {
        int i0 = (b - SB_EMB0) * 256 + tid * 2;
        #pragma unroll
        for (int u = 0; u < 2; u++) {
            int i = i0 + u;
            int n = i >> 5, q = i & 31;
            float4 v = __ldg((const float4*)(emb + (long long)at[n] * DIM) + q);
            *(float4*)(g_H + (long long)n * 512 + q * 4) = v;
        }
    }
}

// ---------------- CSR: hist + lookback scan + scatter ----------------
__global__ void hist_kernel(const int* __restrict__ dst) {
    int e = blockIdx.x * 256 + threadIdx.x;
    if (e < N_EDGES) atomicAdd(&g_cnt[dst[e]], 1);
}

__global__ void scan_lb() {
    __shared__ int sh[256];
    __shared__ int s_excl;
    int b = blockIdx.x, tid = threadIdx.x;
    int n = b * 256 + tid;
    int v = (n < N_NODES) ? g_cnt[n] : 0;
    sh[tid] = v; __syncthreads();
    #pragma unroll
    for (int o = 1; o < 256; o <<= 1) {
        int t = (tid >= o) ? sh[tid - o] : 0;
        __syncthreads();
        sh[tid] += t;
        __syncthreads();
    }
    if (tid == 0) {
        int total = sh[255];
        if (b == 0) {
            g_inclV[0] = total;
            __threadfence();
            g_flag[0] = 2;
            s_excl = 0;
        } else {
            g_aggrV[b] = total;
            __threadfence();
            g_flag[b] = 1;
            int excl = 0, j = b - 1;
            while (true) {
                int f;
                do { f = g_flag[j]; } while (f == 0);
                if (f == 2) { excl += g_inclV[j]; break; }
                excl += g_aggrV[j];
                j--;
            }
            g_inclV[b] = excl + total;
            __threadfence();
            g_flag[b] = 2;
            s_excl = excl;
        }
    }
    __syncthreads();
    if (n < N_NODES) {
        int o = s_excl + sh[tid] - v;
        g_off[n] = o;
        g_cur[n] = o;
    }
    if (n == 0) g_off[N_NODES] = N_EDGES;
}

__global__ void scatter_kernel(const int* __restrict__ src, const int* __restrict__ dst,
                               const float* __restrict__ dist) {
    int e = blockIdx.x * 256 + threadIdx.x;
    if (e >= N_EDGES) return;
    int d = __ldg(dst + e);
    int pos = atomicAdd(&g_cur[d], 1);
    float di = __ldg(dist + e);
    float t = di * ((float)(GRID_G - 1) / 10.0f);
    int gg = (int)(t + 0.5f);
    gg = gg < GRID_G - 1 ? gg : GRID_G - 1;
    g_recP[pos] = (unsigned)__ldg(src + e) | ((unsigned)gg << 16);
}

// ---------------- edge gather (R12 shape + vectorized record load) ----------------
__device__ __forceinline__ void eacc(float4& acc, uint2 tv, uint2 hv) {
    float2 t01 = __half22float2(*(__half2*)&tv.x);
    float2 t23 = __half22float2(*(__half2*)&tv.y);
    float2 h01 = __half22float2(*(__half2*)&hv.x);
    float2 h23 = __half22float2(*(__half2*)&hv.y);
    acc.x = fmaf(t01.x, h01.x, acc.x);
    acc.y = fmaf(t01.y, h01.y, acc.y);
    acc.z = fmaf(t23.x, h23.x, acc.z);
    acc.w = fmaf(t23.y, h23.y, acc.w);
}

__global__ __launch_bounds__(256) void edge_gather(
    const __half* __restrict__ tabp,
    const __half* __restrict__ hn,
    __half* __restrict__ node2)
{
    int wid = threadIdx.x >> 5, lane = threadIdx.x & 31;
    int n = blockIdx.x * 8 + wid;
    if (n >= N_NODES) return;
    int beg = __ldg(&g_off[n]);
    int end = __ldg(&g_off[n + 1]);
    float4 acc = make_float4(0.f, 0.f, 0.f, 0.f);
    int i = beg;
    // align to 4 for vectorized record loads
    for (; i < end && (i & 3); i++) {
        unsigned r = __ldg(&g_recP[i]);
        uint2 tv = __ldg((const uint2*)(tabp + (long long)(r >> 16) * DIM) + lane);
        uint2 hv = __ldg((const uint2*)(hn + (long long)(r & 0xFFFFu) * DIM) + lane);
        eacc(acc, tv, hv);
    }
    for (; i + 4 <= end; i += 4) {
        uint4 rv = __ldg((const uint4*)&g_recP[i]);
        uint2 t0 = __ldg((const uint2*)(tabp + (long long)(rv.x >> 16) * DIM) + lane);
        uint2 t1 = __ldg((const uint2*)(tabp + (long long)(rv.y >> 16) * DIM) + lane);
        uint2 t2 = __ldg((const uint2*)(tabp + (long long)(rv.z >> 16) * DIM) + lane);
        uint2 t3 = __ldg((const uint2*)(tabp + (long long)(rv.w >> 16) * DIM) + lane);
        uint2 h0 = __ldg((const uint2*)(hn + (long long)(rv.x & 0xFFFFu) * DIM) + lane);
        uint2 h1 = __ldg((const uint2*)(hn + (long long)(rv.y & 0xFFFFu) * DIM) + lane);
        uint2 h2 = __ldg((const uint2*)(hn + (long long)(rv.z & 0xFFFFu) * DIM) + lane);
        uint2 h3 = __ldg((const uint2*)(hn + (long long)(rv.w & 0xFFFFu) * DIM) + lane);
        eacc(acc, t0, h0);
        eacc(acc, t1, h1);
        eacc(acc, t2, h2);
        eacc(acc, t3, h3);
    }
    for (; i < end; i++) {
        unsigned r = __ldg(&g_recP[i]);
        uint2 tv = __ldg((const uint2*)(tabp + (long long)(r >> 16) * DIM) + lane);
        uint2 hv = __ldg((const uint2*)(hn + (long long)(r & 0xFFFFu) * DIM) + lane);
        eacc(acc, tv, hv);
    }
    __half2 o01 = __floats2half2_rn(acc.x, acc.y);
    __half2 o23 = __floats2half2_rn(acc.z, acc.w);
    *(uint2*)(node2 + (long long)n * DIM + lane * 4) =
        make_uint2(*(uint32_t*)&o01, *(uint32_t*)&o23);
}

// ---------------- merged: gemm_tab (384 blocks) + gemm_m1 (938 blocks) ----------------
__global__ __launch_bounds__(256) void gemm_tab_m1(
    const float* __restrict__ b_n1, int M)
{
    extern __shared__ uint32_t sm[];
    int tid = threadIdx.x, wid = tid >> 5, lane = tid & 31;
    int mw = wid & 3, nw = wid >> 2;
    int g = lane >> 2, tg = lane & 3;

    if (blockIdx.x < 384) {
        int l = blockIdx.x / 128;
        int r0 = (blockIdx.x % 128) * 64;
        const float* X = g_Spu + (long long)l * GRID_G * DIM;
        __half* Y = g_TabP + (long long)l * GRID_G * DIM;

        load_A_f(sm, X, DIM, 0, r0, GRID_G, tid);
        load_B(sm, OFF_BHI, OFF_BLO,
               g_WfHi + (long long)l * DIM * DIM, g_WfLo + (long long)l * DIM * DIM, tid);
        __syncthreads();

        float acc[8][4];
        #pragma unroll
        for (int t = 0; t < 8; t++)
            #pragma unroll
            for (int i = 0; i < 4; i++) acc[t][i] = 0.0f;
        mma_core2<8>(sm, mw, nw * 64, g, tg, acc, OFF_BHI, OFF_BLO);

        int row0 = r0 + mw * 16 + g, row1 = row0 + 8;
        #pragma unroll
        for (int t = 0; t < 8; t++) {
            int col = nw * 64 + t * 8 + tg * 2;
            float b0 = g_bf[l * DIM + col], b1 = g_bf[l * DIM + col + 1];
            *(__half2*)(Y + (long long)row0 * DIM + col) =
                __floats2half2_rn(acc[t][0] + b0, acc[t][1] + b1);
            *(__half2*)(Y + (long long)row1 * DIM + col) =
                __floats2half2_rn(acc[t][2] + b0, acc[t][3] + b1);
        }
    } else {
        int r0 = (int)(blockIdx.x - 384) * 64;

        load_A_f(sm, g_H, 512, 0, r0, M, tid);
        load_B(sm, OFF_BHI, OFF_BLO, g_WbHi, g_WbLo, tid);
        __syncthreads();

        float acc[8][4];
        #pragma unroll
        for (int t = 0; t < 8; t++)
            #pragma unroll
            for (int i = 0; i < 4; i++) acc[t][i] = 0.0f;
        mma_core2<8>(sm, mw, nw * 64, g, tg, acc, OFF_BHI, OFF_BLO);

        int row0 = r0 + mw * 16 + g, row1 = row0 + 8;
        #pragma unroll
        for (int t = 0; t < 8; t++) {
            int col = nw * 64 + t * 8 + tg * 2;
            float b0 = __ldg(b_n1 + col) + 1.0f;
            float b1 = __ldg(b_n1 + col + 1) + 1.0f;
            if (row0 < M)
                *(__half2*)(g_Hn2 + (long long)row0 * DIM + col) =
                    __floats2half2_rn(acc[t][0] + b0, acc[t][1] + b1);
            if (row1 < M)
                *(__half2*)(g_Hn2 + (long long)row1 * DIM + col) =
                    __floats2half2_rn(acc[t][2] + b0, acc[t][3] + b1);
        }
    }
}

// ---------------- fused: H' = H + sp(Node2@W2+b2)@W3+b3 ; optionally next Hn ----------------
__global__ __launch_bounds__(256) void gemm_m23(
    const __half* __restrict__ X,
    const __half* __restrict__ W2hi, const __half* __restrict__ W2lo,
    const float* __restrict__ b2,
    const __half* __restrict__ W3hi, const __half* __restrict__ W3lo,
    const float* __restrict__ b3,
    const float* __restrict__ Res, int sr,
    float* __restrict__ Y, int sy,
    const __half* __restrict__ W1hi, const __half* __restrict__ W1lo,
    const float* __restrict__ b1n,
    __half* __restrict__ Hn2,
    int has_next, int M)
{
    extern __shared__ uint32_t sm[];
    uint32_t* A = sm + OFF_A;
    int tid = threadIdx.x, wid = tid >> 5, lane = tid & 31;
    int mw = wid & 3, nw = wid >> 2;
    int g = lane >> 2, tg = lane & 3;
    int r0 = blockIdx.x * 64;
    int rl0 = mw * 16 + g, rl1 = rl0 + 8;
    int row0 = r0 + rl0, row1 = row0 + 8;

    load_A_h(sm, X, r0, M, tid);
    load_B(sm, OFF_BHI, OFF_BLO, W2hi, W2lo, tid);
    __syncthreads();

    float acc[8][4];
    #pragma unroll
    for (int t = 0; t < 8; t++)
        #pragma unroll
        for (int i = 0; i < 4; i++) acc[t][i] = 0.0f;
    mma_core2<8>(sm, mw, nw * 64, g, tg, acc, OFF_BHI, OFF_BLO);

    #pragma unroll
    for (int t = 0; t < 8; t++) {
        int col = nw * 64 + t * 8 + tg * 2;
        float b0 = __ldg(b2 + col), b1 = __ldg(b2 + col + 1);
        __half2 v0 = __floats2half2_rn(sp_half(acc[t][0] + b0), sp_half(acc[t][1] + b1));
        __half2 v1 = __floats2half2_rn(sp_half(acc[t][2] + b0), sp_half(acc[t][3] + b1));
        A[rl0 * ASTR + (col >> 1)] = *(uint32_t*)&v0;
        A[rl1 * ASTR + (col >> 1)] = *(uint32_t*)&v1;
    }
    __syncthreads();
    load_B(sm, OFF_BHI, OFF_BLO, W3hi, W3lo, tid);
    __syncthreads();

    #pragma unroll
    for (int t = 0; t < 8; t++)
        #pragma unroll
        for (int i = 0; i < 4; i++) acc[t][i] = 0.0f;
    mma_core2<8>(sm, mw, nw * 64, g, tg, acc, OFF_BHI, OFF_BLO);

    #pragma unroll
    for (int t = 0; t < 8; t++) {
        int col = nw * 64 + t * 8 + tg * 2;
        float b0 = __ldg(b3 + col), b1 = __ldg(b3 + col + 1);
        float y0 = acc[t][0] + b0, y1 = acc[t][1] + b1;
        float y2 = acc[t][2] + b0, y3 = acc[t][3] + b1;
        if (row0 < M) {
            float2 r = *(const float2*)(Res + (long long)row0 * sr + col);
            y0 += r.x; y1 += r.y;
            *(float2*)(Y + (long long)row0 * sy + col) = make_float2(y0, y1);
        }
        if (row1 < M) {
            float2 r = *(const float2*)(Res + (long long)row1 * sr + col);
            y2 += r.x; y3 += r.y;
            *(float2*)(Y + (long long)row1 * sy + col) = make_float2(y2, y3);
        }
        if (has_next) {
            __half2 v0 = __floats2half2_rn(y0, y1);
            __half2 v1 = __floats2half2_rn(y2, y3);
            A[rl0 * ASTR + (col >> 1)] = *(uint32_t*)&v0;
            A[rl1 * ASTR + (col >> 1)] = *(uint32_t*)&v1;
        }
    }
    if (!has_next) return;

    __syncthreads();
    load_B(sm, OFF_BHI, OFF_BLO, W1hi, W1lo, tid);
    __syncthreads();

    #pragma unroll
    for (int t = 0; t < 8; t++)
        #pragma unroll
        for (int i = 0; i < 4; i++) acc[t][i] = 0.0f;
    mma_core2<8>(sm, mw, nw * 64, g, tg, acc, OFF_BHI, OFF_BLO);

    #pragma unroll
    for (int t = 0; t < 8; t++) {
        int col = nw * 64 + t * 8 + tg * 2;
        float b0 = __ldg(b1n + col) + 1.0f;
        float b1 = __ldg(b1n + col + 1) + 1.0f;
        if (row0 < M)
            *(__half2*)(Hn2 + (long long)row0 * DIM + col) =
                __floats2half2_rn(acc[t][0] + b0, acc[t][1] + b1);
        if (row1 < M)
            *(__half2*)(Hn2 + (long long)row1 * DIM + col) =
                __floats2half2_rn(acc[t][2] + b0, acc[t][3] + b1);
    }
}

// ---------------- fused readout ----------------
__global__ __launch_bounds__(256) void gemm_r(
    const float* __restrict__ X,
    const __half* __restrict__ Whi, const __half* __restrict__ Wlo,
    const float* __restrict__ br1, const float* __restrict__ Wr2,
    const float* __restrict__ br2,
    const int* __restrict__ gid, float* __restrict__ out, int M)
{
    extern __shared__ uint32_t sm[];
    __shared__ float res[64];
    int tid = threadIdx.x, wid = tid >> 5, lane = tid & 31;
    int mw = wid & 3, nw = wid >> 2;
    int g = lane >> 2, tg = lane & 3;
    int r0 = blockIdx.x * 64;
    if (tid < 64) res[tid] = 0.0f;

    float acc[4][4];
    #pragma unroll
    for (int t = 0; t < 4; t++)
        #pragma unroll
        for (int i = 0; i < 4; i++) acc[t][i] = 0.0f;

    for (int ch = 0; ch < 4; ch++) {
        load_A_f(sm, X, 512, ch * 128, r0, M, tid);
        load_B_r(sm, Whi, Wlo, ch, tid);
        __syncthreads();
        mma_core2<4>(sm, mw, nw * 32, g, tg, acc, OFF_BHI_R, OFF_BLO_R);
        __syncthreads();
    }

    float p0 = 0.0f, p1 = 0.0f;
    #pragma unroll
    for (int t = 0; t < 4; t++) {
        int col = nw * 32 + t * 8 + tg * 2;
        float b0 = __ldg(br1 + col), b1 = __ldg(br1 + col + 1);
        float w0 = __ldg(Wr2 + col), w1 = __ldg(Wr2 + col + 1);
        p0 += sp_one(acc[t][0] + b0) * w0 + sp_one(acc[t][1] + b1) * w1;
        p1 += sp_one(acc[t][2] + b0) * w0 + sp_one(acc[t][3] + b1) * w1;
    }
    p0 += __shfl_down_sync(0xffffffff, p0, 1);
    p0 += __shfl_down_sync(0xffffffff, p0, 2);
    p1 += __shfl_down_sync(0xffffffff, p1, 1);
    p1 += __shfl_down_sync(0xffffffff, p1, 2);
    if (tg == 0) {
        atomicAdd(&res[mw * 16 + g], p0);
        atomicAdd(&res[mw * 16 + g + 8], p1);
    }
    __syncthreads();
    if (tid < 64) {
        int row = r0 + tid;
        if (row < M) atomicAdd(out + __ldg(gid + row), res[tid] + __ldg(br2));
    }
}

// ---------------- launch ----------------
extern "C" void kernel_launch(void* const* d_in, const int* in_sizes, int n_in,
                              void* d_out, int out_size) {
    const int*   atom_type = (const int*)d_in[0];
    const int*   src  = (const int*)d_in[1];
    const int*   dst  = (const int*)d_in[2];
    const int*   gid  = (const int*)d_in[3];
    const float* dist = (const float*)d_in[4];
    const float* emb  = (const float*)d_in[5];
    const float* W_n1 = (const float*)d_in[6];  const float* b_n1 = (const float*)d_in[7];
    const float* W_c1 = (const float*)d_in[8];  const float* b_c1 = (const float*)d_in[9];
    const float* W_c2 = (const float*)d_in[10]; const float* b_c2 = (const float*)d_in[11];
    const float* W_c3 = (const float*)d_in[12]; const float* b_c3 = (const float*)d_in[13];
    const float* W_n2 = (const float*)d_in[14]; const float* b_n2 = (const float*)d_in[15];
    const float* W_n3 = (const float*)d_in[16]; const float* b_n3 = (const float*)d_in[17];
    const float* W_r1 = (const float*)d_in[18]; const float* b_r1 = (const float*)d_in[19];
    const float* W_r2 = (const float*)d_in[20]; const float* b_r2 = (const float*)d_in[21];
    float* out = (float*)d_out;

    float* H;
    __half *Hn2, *Node2, *TabP;
    __half *WbHi, *WbLo, *WrHi, *WrLo;
    cudaGetSymbolAddress((void**)&H,     g_H);
    cudaGetSymbolAddress((void**)&Hn2,   g_Hn2);
    cudaGetSymbolAddress((void**)&Node2, g_Node2);
    cudaGetSymbolAddress((void**)&TabP,  g_TabP);
    cudaGetSymbolAddress((void**)&WbHi,  g_WbHi);
    cudaGetSymbolAddress((void**)&WbLo,  g_WbLo);
    cudaGetSymbolAddress((void**)&WrHi,  g_WrHi);
    cudaGetSymbolAddress((void**)&WrLo,  g_WrLo);

    cudaFuncSetAttribute(gemm_tab_m1, cudaFuncAttributeMaxDynamicSharedMemorySize, TSMEM_M);
    cudaFuncSetAttribute(gemm_m23,    cudaFuncAttributeMaxDynamicSharedMemorySize, TSMEM_M);
    cudaFuncSetAttribute(gemm_r,      cudaFuncAttributeMaxDynamicSharedMemorySize, TSMEM_R);

    const int M = N_NODES;
    const int GB64 = (M + 63) / 64;     // 938
    const int EB = (N_EDGES + 255) / 256;

    // 1) all independent setup work
    setup1<<<SB_TOTAL, 128>>>(W_c2, b_c2, W_c3, b_c3, W_c1, b_c1,
                              W_n1, W_n2, W_n3, W_r1, atom_type, emb, out);
    // 2-4) CSR build
    hist_kernel<<<EB, 256>>>(dst);
    scan_lb<<<NB_SCAN, 256>>>();
    scatter_kernel<<<EB, 256>>>(src, dst, dist);
    // 5) table GEMM + layer-0 h_new, merged
    gemm_tab_m1<<<384 + GB64, 256, TSMEM_M>>>(b_n1, M);

    for (int l = 0; l < N_LAYERS; l++) {
        edge_gather<<<(N_NODES + 7) / 8, 256>>>(
            TabP + (long long)l * GRID_G * DIM, Hn2, Node2);
        int nl = l + 1;
        int has_next = (nl < N_LAYERS);
        gemm_m23<<<GB64, 256, TSMEM_M>>>(
            Node2,
            WbHi + (long long)(3 + l) * DIM * DIM, WbLo + (long long)(3 + l) * DIM * DIM,
            b_n2 + l * 128,
            WbHi + (long long)(6 + l) * DIM * DIM, WbLo + (long long)(6 + l) * DIM * DIM,
            b_n3 + l * 128,
            H + l * 128, 512, H + nl * 128, 512,
            WbHi + (long long)(has_next ? nl : 0) * DIM * DIM,
            WbLo + (long long)(has_next ? nl : 0) * DIM * DIM,
            b_n1 + (has_next ? nl : 0) * 128,
            Hn2, has_next, M);
    }

    gemm_r<<<GB64, 256, TSMEM_R>>>(H, WrHi, WrLo, b_r1, W_r2, b_r2, gid, out, M);
}

// round 16
// speedup vs baseline: 1.8549x; 1.2865x over previous
#include <cuda_runtime.h>
#include <cuda_fp16.h>
#include <math.h>
#include <stdint.h>

#define N_NODES 60000
#define N_EDGES 600000
#define N_GRAPH 512
#define DIM 128
#define N_LAYERS 3
#define GRID_G 8192
#define NB_SCAN 235      // ceil(60000/256)

// ---------------- device scratch ----------------
__device__ float g_H[(long long)N_NODES * 512];
__device__ __half g_Hn2[(long long)N_NODES * DIM];
__device__ __half g_Node2[(long long)N_NODES * DIM];
__device__ float g_bf[N_LAYERS * DIM];
__device__ float g_Spu[(long long)N_LAYERS * GRID_G * DIM];
__device__ __align__(256) __half g_TabP[(long long)N_LAYERS * GRID_G * DIM];
// fp16 weights (single plane), B-operand layout [N][K]
__device__ __align__(256) __half g_Wb[9 * DIM * DIM];
__device__ __align__(256) __half g_Wf[N_LAYERS * DIM * DIM];
__device__ __align__(256) __half g_Wr[64 * 512];
// CSR build
__device__ int g_cnt[N_NODES];
__device__ int g_off[N_NODES + 1];
__device__ int g_cur[N_NODES];
__device__ __align__(16) unsigned g_recP[N_EDGES + 4];
// lookback scan state
__device__ volatile int g_flag[NB_SCAN];
__device__ volatile int g_aggrV[NB_SCAN];
__device__ volatile int g_inclV[NB_SCAN];

// ---------------- scalar helpers ----------------
__device__ __forceinline__ float sp_half(float x) {
    float bx = 0.5f * x;
    return bx > 14.0f ? x : 2.0f * log1pf(expf(bx));
}
__device__ __forceinline__ float sp_one(float x) {
    return x > 20.0f ? x : log1pf(expf(x));
}

// ---------------- HMMA fp16 ----------------
__device__ __forceinline__ void mma16816h(float* d, const uint32_t* a,
                                          uint32_t b0, uint32_t b1) {
    asm volatile(
        "mma.sync.aligned.m16n8k16.row.col.f32.f16.f16.f32 "
        "{%0,%1,%2,%3}, {%4,%5,%6,%7}, {%8,%9}, {%0,%1,%2,%3};"
        : "+f"(d[0]), "+f"(d[1]), "+f"(d[2]), "+f"(d[3])
        : "r"(a[0]), "r"(a[1]), "r"(a[2]), "r"(a[3]), "r"(b0), "r"(b1));
}

#define ASTR 68
#define A_WORDS (64 * ASTR)            // 4352
#define B_WORDS (128 * ASTR)           // 8704
#define BR_WORDS (64 * ASTR)
#define OFF_A 0
#define OFF_B  A_WORDS
#define TSMEM_M ((A_WORDS + B_WORDS) * 4)   // 52224
#define TSMEM_R ((A_WORDS + BR_WORDS) * 4)  // 34816

// single-product core: acc += A(fp16) @ B(fp16)
template<int NT>
__device__ __forceinline__ void mma_core1(const uint32_t* __restrict__ sm,
                                          int mw, int nwbase, int g, int tg,
                                          float acc[NT][4]) {
    const uint32_t* A = sm + OFF_A;
    const uint32_t* B = sm + OFF_B;
    int ra0 = (mw * 16 + g) * ASTR;
    int ra1 = ra0 + 8 * ASTR;
    #pragma unroll
    for (int ks = 0; ks < 8; ks++) {
        int c = ks * 8 + tg;
        uint32_t ah[4];
        ah[0] = A[ra0 + c];     ah[1] = A[ra1 + c];
        ah[2] = A[ra0 + c + 4]; ah[3] = A[ra1 + c + 4];
        #pragma unroll
        for (int t = 0; t < NT; t++) {
            int rb = (nwbase + t * 8 + g) * ASTR;
            mma16816h(acc[t], ah, B[rb + c], B[rb + c + 4]);
        }
    }
}

// fp32 X tile -> fp16 A smem
__device__ __forceinline__ void load_A_f(uint32_t* sm, const float* __restrict__ X,
                                         int sx, int c0, int r0, int M, int tid) {
    uint32_t* A = sm + OFF_A;
    #pragma unroll
    for (int j = 0; j < 8; j++) {
        int f = tid + j * 256;
        int row = f >> 5, q = f & 31;
        float4 v = make_float4(0.f, 0.f, 0.f, 0.f);
        int gr = r0 + row;
        if (gr < M) v = *(const float4*)(X + (long long)gr * sx + c0 + q * 4);
        __half2 h01 = __floats2half2_rn(v.x, v.y);
        __half2 h23 = __floats2half2_rn(v.z, v.w);
        *(uint2*)(A + row * ASTR + q * 2) =
            make_uint2(*(uint32_t*)&h01, *(uint32_t*)&h23);
    }
}

// fp16 X tile [M][128] -> A smem
__device__ __forceinline__ void load_A_h(uint32_t* sm, const __half* __restrict__ X,
                                         int r0, int M, int tid) {
    uint32_t* A = sm + OFF_A;
    #pragma unroll
    for (int j = 0; j < 4; j++) {
        int idx = tid + j * 256;
        int row = idx >> 4, q = idx & 15;
        uint4 v = make_uint4(0u, 0u, 0u, 0u);
        int gr = r0 + row;
        if (gr < M) v = *((const uint4*)(X + (long long)gr * DIM) + q);
        *(uint4*)(A + row * ASTR + q * 4) = v;
    }
}

// W [128 rows][64 words] = 2048 uint4 -> B smem  (FULL 128 rows!)
__device__ __forceinline__ void load_B(uint32_t* sm, const __half* __restrict__ W, int tid) {
    uint32_t* B = sm + OFF_B;
    const uint4* s1 = (const uint4*)W;
    #pragma unroll
    for (int j = 0; j < 8; j++) {
        int i = tid + j * 256;              // 2048 uint4 = 128 rows x 16
        int row = i >> 4, cq = (i & 15) * 4;
        *(uint4*)(B + row * ASTR + cq) = s1[i];
    }
}

// readout B: 64 rows, K-chunk of 512-row source (1024 uint4)
__device__ __forceinline__ void load_B_r(uint32_t* sm, const __half* __restrict__ W,
                                         int chunk, int tid) {
    uint32_t* B = sm + OFF_B;
    const uint4* s1 = (const uint4*)W;
    #pragma unroll
    for (int j = 0; j < 4; j++) {
        int i = tid + j * 256;              // 1024 uint4 = 64 rows x 16
        int row = i >> 4, q = i & 15;
        int si = row * 64 + chunk * 16 + q;
        *(uint4*)(B + row * ASTR + q * 4) = s1[si];
    }
}

// ---------------- setup1 ----------------
#define SB_SPU0  384
#define SB_PW0   3456
#define SB_PR0   3600
#define SB_ZC0   3632
#define SB_MS0   4101
#define SB_EMB0  4102
#define SB_TOTAL (4102 + 7500)

__global__ void setup1(const float* __restrict__ Wc2, const float* __restrict__ bc2,
                       const float* __restrict__ Wc3, const float* __restrict__ bc3,
                       const float* __restrict__ Wc1, const float* __restrict__ bc1,
                       const float* __restrict__ Wn1, const float* __restrict__ Wn2,
                       const float* __restrict__ Wn3, const float* __restrict__ Wr1,
                       const int* __restrict__ at, const float* __restrict__ emb,
                       float* __restrict__ out) {
    __shared__ float ssm[30 * DIM + DIM + 32];
    int b = blockIdx.x, tid = threadIdx.x;
    if (b < SB_SPU0) {
        int l = b >> 7, k = b & 127, j = tid;
        float* row = ssm;
        row[j] = Wc2[((long long)l * DIM + k) * DIM + j];
        __syncthreads();
        float acc = 0.0f;
        #pragma unroll 4
        for (int m = 0; m < DIM; m++)
            acc += row[m] * Wc3[((long long)l * DIM + m) * DIM + j];
        g_Wf[(long long)l * DIM * DIM + j * DIM + k] = __float2half_rn(acc);
        if (k == 0) {
            float bacc = bc3[l * DIM + j];
            #pragma unroll 4
            for (int m = 0; m < DIM; m++)
                bacc += bc2[l * DIM + m] * Wc3[((long long)l * DIM + m) * DIM + j];
            g_bf[l * DIM + j] = bacc;
        }
    } else if (b < SB_PW0) {
        int idx = b - SB_SPU0;
        int x = idx & 1023, l = idx >> 10;
        float* wc = ssm;
        float* bc = ssm + 30 * DIM;
        float* rbf = ssm + 30 * DIM + DIM;
        const float* W = Wc1 + (long long)l * 30 * DIM;
        for (int i = tid; i < 30 * DIM; i += 128) wc[i] = W[i];
        bc[tid] = bc1[l * DIM + tid];
        __syncthreads();
        for (int gi = 0; gi < 8; gi++) {
            int g = x * 8 + gi;
            if (tid < 30) {
                float dg = (float)g * (10.0f / (float)(GRID_G - 1));
                float c = (float)tid * (10.0f / 29.0f);
                float dd = dg - c;
                rbf[tid] = expf(-dd * dd * 2.9f);
            }
            __syncthreads();
            float u = bc[tid];
            #pragma unroll
            for (int r = 0; r < 30; r++)
                u += rbf[r] * wc[r * DIM + tid];
            g_Spu[((long long)l * GRID_G + g) * DIM + tid] = sp_half(u);
            __syncthreads();
        }
    } else if (b < SB_PR0) {
        int idx = b - SB_PW0;
        int m = idx % 9, y = idx / 9;
        const float* src = (m < 3 ? Wn1 : (m < 6 ? Wn2 : Wn3)) + (long long)(m % 3) * DIM * DIM;
        __half* dh = g_Wb + (long long)m * DIM * DIM;
        int idx0 = y * 1024;
        #pragma unroll
        for (int i = 0; i < 8; i++) {
            int f = idx0 + i * 128 + tid;
            int k = f >> 7, n = f & 127;
            dh[n * DIM + k] = __float2half_rn(src[f]);
        }
    } else if (b < SB_ZC0) {
        int idx = (b - SB_PR0) * 1024 + tid;
        #pragma unroll
        for (int i = 0; i < 8; i++) {
            int f = idx + i * 128;
            int k = f >> 6, n = f & 63;
            g_Wr[n * 512 + k] = __float2half_rn(Wr1[f]);
        }
    } else if (b < SB_MS0) {
        int i = (b - SB_ZC0) * 128 + tid;
        if (i < N_NODES) g_cnt[i] = 0;
    } else if (b < SB_EMB0) {
        #pragma unroll
        for (int i = 0; i < 4; i++) out[tid + i * 128] = 0.0f;
        g_flag[tid] = 0;
        if (tid < NB_SCAN - 128) g_flag[tid + 128] = 0;
    } else {
        int i0 = (b - SB_EMB0) * 256 + tid * 2;
        #pragma unroll
        for (int u = 0; u < 2; u++) {
            int i = i0 + u;
            int n = i >> 5, q = i & 31;
            float4 v = __ldg((const float4*)(emb + (long long)at[n] * DIM) + q);
            *(float4*)(g_H + (long long)n * 512 + q * 4) = v;
        }
    }
}

// ---------------- CSR: hist + lookback scan + scatter ----------------
__global__ void hist_kernel(const int* __restrict__ dst) {
    int e = blockIdx.x * 256 + threadIdx.x;
    if (e < N_EDGES) atomicAdd(&g_cnt[dst[e]], 1);
}

__global__ void scan_lb() {
    __shared__ int sh[256];
    __shared__ int s_excl;
    int b = blockIdx.x, tid = threadIdx.x;
    int n = b * 256 + tid;
    int v = (n < N_NODES) ? g_cnt[n] : 0;
    sh[tid] = v; __syncthreads();
    #pragma unroll
    for (int o = 1; o < 256; o <<= 1) {
        int t = (tid >= o) ? sh[tid - o] : 0;
        __syncthreads();
        sh[tid] += t;
        __syncthreads();
    }
    if (tid == 0) {
        int total = sh[255];
        if (b == 0) {
            g_inclV[0] = total;
            __threadfence();
            g_flag[0] = 2;
            s_excl = 0;
        } else {
            g_aggrV[b] = total;
            __threadfence();
            g_flag[b] = 1;
            int excl = 0, j = b - 1;
            while (true) {
                int f;
                do { f = g_flag[j]; } while (f == 0);
                if (f == 2) { excl += g_inclV[j]; break; }
                excl += g_aggrV[j];
                j--;
            }
            g_inclV[b] = excl + total;
            __threadfence();
            g_flag[b] = 2;
            s_excl = excl;
        }
    }
    __syncthreads();
    if (n < N_NODES) {
        int o = s_excl + sh[tid] - v;
        g_off[n] = o;
        g_cur[n] = o;
    }
    if (n == 0) g_off[N_NODES] = N_EDGES;
}

__global__ void scatter_kernel(const int* __restrict__ src, const int* __restrict__ dst,
                               const float* __restrict__ dist) {
    int e = blockIdx.x * 256 + threadIdx.x;
    if (e >= N_EDGES) return;
    int d = __ldg(dst + e);
    int pos = atomicAdd(&g_cur[d], 1);
    float di = __ldg(dist + e);
    float t = di * ((float)(GRID_G - 1) / 10.0f);
    int gg = (int)(t + 0.5f);
    gg = gg < GRID_G - 1 ? gg : GRID_G - 1;
    g_recP[pos] = (unsigned)__ldg(src + e) | ((unsigned)gg << 16);
}

// ---------------- edge gather (R12 shape) ----------------
__device__ __forceinline__ void eacc(float4& acc, uint2 tv, uint2 hv) {
    float2 t01 = __half22float2(*(__half2*)&tv.x);
    float2 t23 = __half22float2(*(__half2*)&tv.y);
    float2 h01 = __half22float2(*(__half2*)&hv.x);
    float2 h23 = __half22float2(*(__half2*)&hv.y);
    acc.x = fmaf(t01.x, h01.x, acc.x);
    acc.y = fmaf(t01.y, h01.y, acc.y);
    acc.z = fmaf(t23.x, h23.x, acc.z);
    acc.w = fmaf(t23.y, h23.y, acc.w);
}

__global__ __launch_bounds__(256) void edge_gather(
    const __half* __restrict__ tabp,
    const __half* __restrict__ hn,
    __half* __restrict__ node2)
{
    int wid = threadIdx.x >> 5, lane = threadIdx.x & 31;
    int n = blockIdx.x * 8 + wid;
    if (n >= N_NODES) return;
    int beg = __ldg(&g_off[n]);
    int end = __ldg(&g_off[n + 1]);
    float4 acc = make_float4(0.f, 0.f, 0.f, 0.f);
    int i = beg;
    for (; i + 4 <= end; i += 4) {
        unsigned r0 = __ldg(&g_recP[i]);
        unsigned r1 = __ldg(&g_recP[i + 1]);
        unsigned r2 = __ldg(&g_recP[i + 2]);
        unsigned r3 = __ldg(&g_recP[i + 3]);
        uint2 t0 = __ldg((const uint2*)(tabp + (long long)(r0 >> 16) * DIM) + lane);
        uint2 t1 = __ldg((const uint2*)(tabp + (long long)(r1 >> 16) * DIM) + lane);
        uint2 t2 = __ldg((const uint2*)(tabp + (long long)(r2 >> 16) * DIM) + lane);
        uint2 t3 = __ldg((const uint2*)(tabp + (long long)(r3 >> 16) * DIM) + lane);
        uint2 h0 = __ldg((const uint2*)(hn + (long long)(r0 & 0xFFFFu) * DIM) + lane);
        uint2 h1 = __ldg((const uint2*)(hn + (long long)(r1 & 0xFFFFu) * DIM) + lane);
        uint2 h2 = __ldg((const uint2*)(hn + (long long)(r2 & 0xFFFFu) * DIM) + lane);
        uint2 h3 = __ldg((const uint2*)(hn + (long long)(r3 & 0xFFFFu) * DIM) + lane);
        eacc(acc, t0, h0);
        eacc(acc, t1, h1);
        eacc(acc, t2, h2);
        eacc(acc, t3, h3);
    }
    for (; i < end; i++) {
        unsigned r = __ldg(&g_recP[i]);
        uint2 tv = __ldg((const uint2*)(tabp + (long long)(r >> 16) * DIM) + lane);
        uint2 hv = __ldg((const uint2*)(hn + (long long)(r & 0xFFFFu) * DIM) + lane);
        eacc(acc, tv, hv);
    }
    __half2 o01 = __floats2half2_rn(acc.x, acc.y);
    __half2 o23 = __floats2half2_rn(acc.z, acc.w);
    *(uint2*)(node2 + (long long)n * DIM + lane * 4) =
        make_uint2(*(uint32_t*)&o01, *(uint32_t*)&o23);
}

// ---------------- merged: gemm_tab (384 blocks) + gemm_m1 (938 blocks) ----------------
__global__ __launch_bounds__(256) void gemm_tab_m1(
    const float* __restrict__ b_n1, int M)
{
    extern __shared__ uint32_t sm[];
    int tid = threadIdx.x, wid = tid >> 5, lane = tid & 31;
    int mw = wid & 3, nw = wid >> 2;
    int g = lane >> 2, tg = lane & 3;

    if (blockIdx.x < 384) {
        int l = blockIdx.x / 128;
        int r0 = (blockIdx.x % 128) * 64;
        const float* X = g_Spu + (long long)l * GRID_G * DIM;
        __half* Y = g_TabP + (long long)l * GRID_G * DIM;

        load_A_f(sm, X, DIM, 0, r0, GRID_G, tid);
        load_B(sm, g_Wf + (long long)l * DIM * DIM, tid);
        __syncthreads();

        float acc[8][4];
        #pragma unroll
        for (int t = 0; t < 8; t++)
            #pragma unroll
            for (int i = 0; i < 4; i++) acc[t][i] = 0.0f;
        mma_core1<8>(sm, mw, nw * 64, g, tg, acc);

        int row0 = r0 + mw * 16 + g, row1 = row0 + 8;
        #pragma unroll
        for (int t = 0; t < 8; t++) {
            int col = nw * 64 + t * 8 + tg * 2;
            float b0 = g_bf[l * DIM + col], b1 = g_bf[l * DIM + col + 1];
            *(__half2*)(Y + (long long)row0 * DIM + col) =
                __floats2half2_rn(acc[t][0] + b0, acc[t][1] + b1);
            *(__half2*)(Y + (long long)row1 * DIM + col) =
                __floats2half2_rn(acc[t][2] + b0, acc[t][3] + b1);
        }
    } else {
        int r0 = (int)(blockIdx.x - 384) * 64;

        load_A_f(sm, g_H, 512, 0, r0, M, tid);
        load_B(sm, g_Wb, tid);
        __syncthreads();

        float acc[8][4];
        #pragma unroll
        for (int t = 0; t < 8; t++)
            #pragma unroll
            for (int i = 0; i < 4; i++) acc[t][i] = 0.0f;
        mma_core1<8>(sm, mw, nw * 64, g, tg, acc);

        int row0 = r0 + mw * 16 + g, row1 = row0 + 8;
        #pragma unroll
        for (int t = 0; t < 8; t++) {
            int col = nw * 64 + t * 8 + tg * 2;
            float b0 = __ldg(b_n1 + col) + 1.0f;
            float b1 = __ldg(b_n1 + col + 1) + 1.0f;
            if (row0 < M)
                *(__half2*)(g_Hn2 + (long long)row0 * DIM + col) =
                    __floats2half2_rn(acc[t][0] + b0, acc[t][1] + b1);
            if (row1 < M)
                *(__half2*)(g_Hn2 + (long long)row1 * DIM + col) =
                    __floats2half2_rn(acc[t][2] + b0, acc[t][3] + b1);
        }
    }
}

// ---------------- fused: H' = H + sp(Node2@W2+b2)@W3+b3 ; optionally next Hn ----------------
__global__ __launch_bounds__(256) void gemm_m23(
    const __half* __restrict__ X,
    const __half* __restrict__ W2, const float* __restrict__ b2,
    const __half* __restrict__ W3, const float* __restrict__ b3,
    const float* __restrict__ Res, int sr,
    float* __restrict__ Y, int sy,
    const __half* __restrict__ W1, const float* __restrict__ b1n,
    __half* __restrict__ Hn2,
    int has_next, int M)
{
    extern __shared__ uint32_t sm[];
    uint32_t* A = sm + OFF_A;
    int tid = threadIdx.x, wid = tid >> 5, lane = tid & 31;
    int mw = wid & 3, nw = wid >> 2;
    int g = lane >> 2, tg = lane & 3;
    int r0 = blockIdx.x * 64;
    int rl0 = mw * 16 + g, rl1 = rl0 + 8;
    int row0 = r0 + rl0, row1 = row0 + 8;

    load_A_h(sm, X, r0, M, tid);
    load_B(sm, W2, tid);
    __syncthreads();

    float acc[8][4];
    #pragma unroll
    for (int t = 0; t < 8; t++)
        #pragma unroll
        for (int i = 0; i < 4; i++) acc[t][i] = 0.0f;
    mma_core1<8>(sm, mw, nw * 64, g, tg, acc);

    #pragma unroll
    for (int t = 0; t < 8; t++) {
        int col = nw * 64 + t * 8 + tg * 2;
        float b0 = __ldg(b2 + col), b1 = __ldg(b2 + col + 1);
        __half2 v0 = __floats2half2_rn(sp_half(acc[t][0] + b0), sp_half(acc[t][1] + b1));
        __half2 v1 = __floats2half2_rn(sp_half(acc[t][2] + b0), sp_half(acc[t][3] + b1));
        A[rl0 * ASTR + (col >> 1)] = *(uint32_t*)&v0;
        A[rl1 * ASTR + (col >> 1)] = *(uint32_t*)&v1;
    }
    __syncthreads();
    load_B(sm, W3, tid);
    __syncthreads();

    #pragma unroll
    for (int t = 0; t < 8; t++)
        #pragma unroll
        for (int i = 0; i < 4; i++) acc[t][i] = 0.0f;
    mma_core1<8>(sm, mw, nw * 64, g, tg, acc);

    #pragma unroll
    for (int t = 0; t < 8; t++) {
        int col = nw * 64 + t * 8 + tg * 2;
        float b0 = __ldg(b3 + col), b1 = __ldg(b3 + col + 1);
        float y0 = acc[t][0] + b0, y1 = acc[t][1] + b1;
        float y2 = acc[t][2] + b0, y3 = acc[t][3] + b1;
        if (row0 < M) {
            float2 r = *(const float2*)(Res + (long long)row0 * sr + col);
            y0 += r.x; y1 += r.y;
            *(float2*)(Y + (long long)row0 * sy + col) = make_float2(y0, y1);
        }
        if (row1 < M) {
            float2 r = *(const float2*)(Res + (long long)row1 * sr + col);
            y2 += r.x; y3 += r.y;
            *(float2*)(Y + (long long)row1 * sy + col) = make_float2(y2, y3);
        }
        if (has_next) {
            __half2 v0 = __floats2half2_rn(y0, y1);
            __half2 v1 = __floats2half2_rn(y2, y3);
            A[rl0 * ASTR + (col >> 1)] = *(uint32_t*)&v0;
            A[rl1 * ASTR + (col >> 1)] = *(uint32_t*)&v1;
        }
    }
    if (!has_next) return;

    __syncthreads();
    load_B(sm, W1, tid);
    __syncthreads();

    #pragma unroll
    for (int t = 0; t < 8; t++)
        #pragma unroll
        for (int i = 0; i < 4; i++) acc[t][i] = 0.0f;
    mma_core1<8>(sm, mw, nw * 64, g, tg, acc);

    #pragma unroll
    for (int t = 0; t < 8; t++) {
        int col = nw * 64 + t * 8 + tg * 2;
        float b0 = __ldg(b1n + col) + 1.0f;
        float b1 = __ldg(b1n + col + 1) + 1.0f;
        if (row0 < M)
            *(__half2*)(Hn2 + (long long)row0 * DIM + col) =
                __floats2half2_rn(acc[t][0] + b0, acc[t][1] + b1);
        if (row1 < M)
            *(__half2*)(Hn2 + (long long)row1 * DIM + col) =
                __floats2half2_rn(acc[t][2] + b0, acc[t][3] + b1);
    }
}

// ---------------- fused readout ----------------
__global__ __launch_bounds__(256) void gemm_r(
    const float* __restrict__ X,
    const __half* __restrict__ W,
    const float* __restrict__ br1, const float* __restrict__ Wr2,
    const float* __restrict__ br2,
    const int* __restrict__ gid, float* __restrict__ out, int M)
{
    extern __shared__ uint32_t sm[];
    __shared__ float res[64];
    int tid = threadIdx.x, wid = tid >> 5, lane = tid & 31;
    int mw = wid & 3, nw = wid >> 2;
    int g = lane >> 2, tg = lane & 3;
    int r0 = blockIdx.x * 64;
    if (tid < 64) res[tid] = 0.0f;

    float acc[4][4];
    #pragma unroll
    for (int t = 0; t < 4; t++)
        #pragma unroll
        for (int i = 0; i < 4; i++) acc[t][i] = 0.0f;

    for (int ch = 0; ch < 4; ch++) {
        load_A_f(sm, X, 512, ch * 128, r0, M, tid);
        load_B_r(sm, W, ch, tid);
        __syncthreads();
        mma_core1<4>(sm, mw, nw * 32, g, tg, acc);
        __syncthreads();
    }

    float p0 = 0.0f, p1 = 0.0f;
    #pragma unroll
    for (int t = 0; t < 4; t++) {
        int col = nw * 32 + t * 8 + tg * 2;
        float b0 = __ldg(br1 + col), b1 = __ldg(br1 + col + 1);
        float w0 = __ldg(Wr2 + col), w1 = __ldg(Wr2 + col + 1);
        p0 += sp_one(acc[t][0] + b0) * w0 + sp_one(acc[t][1] + b1) * w1;
        p1 += sp_one(acc[t][2] + b0) * w0 + sp_one(acc[t][3] + b1) * w1;
    }
    p0 += __shfl_down_sync(0xffffffff, p0, 1);
    p0 += __shfl_down_sync(0xffffffff, p0, 2);
    p1 += __shfl_down_sync(0xffffffff, p1, 1);
    p1 += __shfl_down_sync(0xffffffff, p1, 2);
    if (tg == 0) {
        atomicAdd(&res[mw * 16 + g], p0);
        atomicAdd(&res[mw * 16 + g + 8], p1);
    }
    __syncthreads();
    if (tid < 64) {
        int row = r0 + tid;
        if (row < M) atomicAdd(out + __ldg(gid + row), res[tid] + __ldg(br2));
    }
}

// ---------------- launch ----------------
extern "C" void kernel_launch(void* const* d_in, const int* in_sizes, int n_in,
                              void* d_out, int out_size) {
    const int*   atom_type = (const int*)d_in[0];
    const int*   src  = (const int*)d_in[1];
    const int*   dst  = (const int*)d_in[2];
    const int*   gid  = (const int*)d_in[3];
    const float* dist = (const float*)d_in[4];
    const float* emb  = (const float*)d_in[5];
    const float* W_n1 = (const float*)d_in[6];  const float* b_n1 = (const float*)d_in[7];
    const float* W_c1 = (const float*)d_in[8];  const float* b_c1 = (const float*)d_in[9];
    const float* W_c2 = (const float*)d_in[10]; const float* b_c2 = (const float*)d_in[11];
    const float* W_c3 = (const float*)d_in[12]; const float* b_c3 = (const float*)d_in[13];
    const float* W_n2 = (const float*)d_in[14]; const float* b_n2 = (const float*)d_in[15];
    const float* W_n3 = (const float*)d_in[16]; const float* b_n3 = (const float*)d_in[17];
    const float* W_r1 = (const float*)d_in[18]; const float* b_r1 = (const float*)d_in[19];
    const float* W_r2 = (const float*)d_in[20]; const float* b_r2 = (const float*)d_in[21];
    float* out = (float*)d_out;

    float* H;
    __half *Hn2, *Node2, *TabP, *Wb, *Wr;
    cudaGetSymbolAddress((void**)&H,     g_H);
    cudaGetSymbolAddress((void**)&Hn2,   g_Hn2);
    cudaGetSymbolAddress((void**)&Node2, g_Node2);
    cudaGetSymbolAddress((void**)&TabP,  g_TabP);
    cudaGetSymbolAddress((void**)&Wb,    g_Wb);
    cudaGetSymbolAddress((void**)&Wr,    g_Wr);

    cudaFuncSetAttribute(gemm_tab_m1, cudaFuncAttributeMaxDynamicSharedMemorySize, TSMEM_M);
    cudaFuncSetAttribute(gemm_m23,    cudaFuncAttributeMaxDynamicSharedMemorySize, TSMEM_M);
    cudaFuncSetAttribute(gemm_r,      cudaFuncAttributeMaxDynamicSharedMemorySize, TSMEM_R);

    const int M = N_NODES;
    const int GB64 = (M + 63) / 64;     // 938
    const int EB = (N_EDGES + 255) / 256;

    setup1<<<SB_TOTAL, 128>>>(W_c2, b_c2, W_c3, b_c3, W_c1, b_c1,
                              W_n1, W_n2, W_n3, W_r1, atom_type, emb, out);
    hist_kernel<<<EB, 256>>>(dst);
    scan_lb<<<NB_SCAN, 256>>>();
    scatter_kernel<<<EB, 256>>>(src, dst, dist);
    gemm_tab_m1<<<384 + GB64, 256, TSMEM_M>>>(b_n1, M);

    for (int l = 0; l < N_LAYERS; l++) {
        edge_gather<<<(N_NODES + 7) / 8, 256>>>(
            TabP + (long long)l * GRID_G * DIM, Hn2, Node2);
        int nl = l + 1;
        int has_next = (nl < N_LAYERS);
        gemm_m23<<<GB64, 256, TSMEM_M>>>(
            Node2,
            Wb + (long long)(3 + l) * DIM * DIM, b_n2 + l * 128,
            Wb + (long long)(6 + l) * DIM * DIM, b_n3 + l * 128,
            H + l * 128, 512, H + nl * 128, 512,
            Wb + (long long)(has_next ? nl : 0) * DIM * DIM,
            b_n1 + (has_next ? nl : 0) * 128,
            Hn2, has_next, M);
    }

    gemm_r<<<GB64, 256, TSMEM_R>>>(H, Wr, b_r1, W_r2, b_r2, gid, out, M);
}

// round 17
// speedup vs baseline: 1.9748x; 1.0646x over previous
#include <cuda_runtime.h>
#include <cuda_fp16.h>
#include <math.h>
#include <stdint.h>

#define N_NODES 60000
#define N_EDGES 600000
#define N_GRAPH 512
#define DIM 128
#define N_LAYERS 3
#define GRID_G 8192
#define NB_SCAN 235      // ceil(60000/256)

// ---------------- device scratch ----------------
__device__ __half g_H[(long long)N_NODES * 512];     // hcat levels 0..3, fp16
__device__ __half g_Hn2[(long long)N_NODES * DIM];
__device__ __half g_Node2[(long long)N_NODES * DIM];
__device__ float g_bf[N_LAYERS * DIM];
__device__ float g_Spu[(long long)N_LAYERS * GRID_G * DIM];
__device__ __align__(256) __half g_TabP[(long long)N_LAYERS * GRID_G * DIM];
// fp16 weights (single plane), B-operand layout [N][K]
__device__ __align__(256) __half g_Wb[9 * DIM * DIM];
__device__ __align__(256) __half g_Wf[N_LAYERS * DIM * DIM];
__device__ __align__(256) __half g_Wr[64 * 512];
// CSR build
__device__ int g_cnt[N_NODES];
__device__ int g_off[N_NODES + 1];
__device__ int g_cur[N_NODES];
__device__ __align__(16) unsigned g_recP[N_EDGES + 4];
// lookback scan state
__device__ volatile int g_flag[NB_SCAN];
__device__ volatile int g_aggrV[NB_SCAN];
__device__ volatile int g_inclV[NB_SCAN];

// ---------------- scalar helpers ----------------
__device__ __forceinline__ float sp_half(float x) {
    float bx = 0.5f * x;
    return bx > 14.0f ? x : 2.0f * log1pf(expf(bx));
}
__device__ __forceinline__ float sp_one(float x) {
    return x > 20.0f ? x : log1pf(expf(x));
}

// ---------------- HMMA fp16 ----------------
__device__ __forceinline__ void mma16816h(float* d, const uint32_t* a,
                                          uint32_t b0, uint32_t b1) {
    asm volatile(
        "mma.sync.aligned.m16n8k16.row.col.f32.f16.f16.f32 "
        "{%0,%1,%2,%3}, {%4,%5,%6,%7}, {%8,%9}, {%0,%1,%2,%3};"
        : "+f"(d[0]), "+f"(d[1]), "+f"(d[2]), "+f"(d[3])
        : "r"(a[0]), "r"(a[1]), "r"(a[2]), "r"(a[3]), "r"(b0), "r"(b1));
}

#define ASTR 68
#define A_WORDS (64 * ASTR)            // 4352
#define B_WORDS (128 * ASTR)           // 8704
#define BR_WORDS (64 * ASTR)
#define OFF_A 0
#define OFF_B  A_WORDS
#define TSMEM_M ((A_WORDS + B_WORDS) * 4)   // 52224
#define TSMEM_R ((A_WORDS + BR_WORDS) * 4)  // 34816

// single-product core: acc += A(fp16) @ B(fp16)
template<int NT>
__device__ __forceinline__ void mma_core1(const uint32_t* __restrict__ sm,
                                          int mw, int nwbase, int g, int tg,
                                          float acc[NT][4]) {
    const uint32_t* A = sm + OFF_A;
    const uint32_t* B = sm + OFF_B;
    int ra0 = (mw * 16 + g) * ASTR;
    int ra1 = ra0 + 8 * ASTR;
    #pragma unroll
    for (int ks = 0; ks < 8; ks++) {
        int c = ks * 8 + tg;
        uint32_t ah[4];
        ah[0] = A[ra0 + c];     ah[1] = A[ra1 + c];
        ah[2] = A[ra0 + c + 4]; ah[3] = A[ra1 + c + 4];
        #pragma unroll
        for (int t = 0; t < NT; t++) {
            int rb = (nwbase + t * 8 + g) * ASTR;
            mma16816h(acc[t], ah, B[rb + c], B[rb + c + 4]);
        }
    }
}

// fp32 X tile -> fp16 A smem
__device__ __forceinline__ void load_A_f(uint32_t* sm, const float* __restrict__ X,
                                         int sx, int c0, int r0, int M, int tid) {
    uint32_t* A = sm + OFF_A;
    #pragma unroll
    for (int j = 0; j < 8; j++) {
        int f = tid + j * 256;
        int row = f >> 5, q = f & 31;
        float4 v = make_float4(0.f, 0.f, 0.f, 0.f);
        int gr = r0 + row;
        if (gr < M) v = *(const float4*)(X + (long long)gr * sx + c0 + q * 4);
        __half2 h01 = __floats2half2_rn(v.x, v.y);
        __half2 h23 = __floats2half2_rn(v.z, v.w);
        *(uint2*)(A + row * ASTR + q * 2) =
            make_uint2(*(uint32_t*)&h01, *(uint32_t*)&h23);
    }
}

// fp16 X tile (stride sx halfs, col offset c0) -> A smem
__device__ __forceinline__ void load_A_h(uint32_t* sm, const __half* __restrict__ X,
                                         int sx, int c0, int r0, int M, int tid) {
    uint32_t* A = sm + OFF_A;
    #pragma unroll
    for (int j = 0; j < 4; j++) {
        int idx = tid + j * 256;
        int row = idx >> 4, q = idx & 15;
        uint4 v = make_uint4(0u, 0u, 0u, 0u);
        int gr = r0 + row;
        if (gr < M) v = *((const uint4*)(X + (long long)gr * sx + c0) + q);
        *(uint4*)(A + row * ASTR + q * 4) = v;
    }
}

// W [128 rows][64 words] = 2048 uint4 -> B smem
__device__ __forceinline__ void load_B(uint32_t* sm, const __half* __restrict__ W, int tid) {
    uint32_t* B = sm + OFF_B;
    const uint4* s1 = (const uint4*)W;
    #pragma unroll
    for (int j = 0; j < 8; j++) {
        int i = tid + j * 256;
        int row = i >> 4, cq = (i & 15) * 4;
        *(uint4*)(B + row * ASTR + cq) = s1[i];
    }
}

// readout B: 64 rows, K-chunk of 512-row source (1024 uint4)
__device__ __forceinline__ void load_B_r(uint32_t* sm, const __half* __restrict__ W,
                                         int chunk, int tid) {
    uint32_t* B = sm + OFF_B;
    const uint4* s1 = (const uint4*)W;
    #pragma unroll
    for (int j = 0; j < 4; j++) {
        int i = tid + j * 256;
        int row = i >> 4, q = i & 15;
        int si = row * 64 + chunk * 16 + q;
        *(uint4*)(B + row * ASTR + q * 4) = s1[si];
    }
}

// ---------------- setup1 ----------------
#define SB_SPU0  384
#define SB_PW0   3456
#define SB_PR0   3600
#define SB_ZC0   3632
#define SB_MS0   4101
#define SB_EMB0  4102
#define SB_TOTAL (4102 + 7500)

__global__ void setup1(const float* __restrict__ Wc2, const float* __restrict__ bc2,
                       const float* __restrict__ Wc3, const float* __restrict__ bc3,
                       const float* __restrict__ Wc1, const float* __restrict__ bc1,
                       const float* __restrict__ Wn1, const float* __restrict__ Wn2,
                       const float* __restrict__ Wn3, const float* __restrict__ Wr1,
                       const int* __restrict__ at, const float* __restrict__ emb,
                       float* __restrict__ out) {
    __shared__ float ssm[30 * DIM + DIM + 32];
    int b = blockIdx.x, tid = threadIdx.x;
    if (b < SB_SPU0) {
        int l = b >> 7, k = b & 127, j = tid;
        float* row = ssm;
        row[j] = Wc2[((long long)l * DIM + k) * DIM + j];
        __syncthreads();
        float acc = 0.0f;
        #pragma unroll 4
        for (int m = 0; m < DIM; m++)
            acc += row[m] * Wc3[((long long)l * DIM + m) * DIM + j];
        g_Wf[(long long)l * DIM * DIM + j * DIM + k] = __float2half_rn(acc);
        if (k == 0) {
            float bacc = bc3[l * DIM + j];
            #pragma unroll 4
            for (int m = 0; m < DIM; m++)
                bacc += bc2[l * DIM + m] * Wc3[((long long)l * DIM + m) * DIM + j];
            g_bf[l * DIM + j] = bacc;
        }
    } else if (b < SB_PW0) {
        int idx = b - SB_SPU0;
        int x = idx & 1023, l = idx >> 10;
        float* wc = ssm;
        float* bc = ssm + 30 * DIM;
        float* rbf = ssm + 30 * DIM + DIM;
        const float* W = Wc1 + (long long)l * 30 * DIM;
        for (int i = tid; i < 30 * DIM; i += 128) wc[i] = W[i];
        bc[tid] = bc1[l * DIM + tid];
        __syncthreads();
        for (int gi = 0; gi < 8; gi++) {
            int g = x * 8 + gi;
            if (tid < 30) {
                float dg = (float)g * (10.0f / (float)(GRID_G - 1));
                float c = (float)tid * (10.0f / 29.0f);
                float dd = dg - c;
                rbf[tid] = expf(-dd * dd * 2.9f);
            }
            __syncthreads();
            float u = bc[tid];
            #pragma unroll
            for (int r = 0; r < 30; r++)
                u += rbf[r] * wc[r * DIM + tid];
            g_Spu[((long long)l * GRID_G + g) * DIM + tid] = sp_half(u);
            __syncthreads();
        }
    } else if (b < SB_PR0) {
        int idx = b - SB_PW0;
        int m = idx % 9, y = idx / 9;
        const float* src = (m < 3 ? Wn1 : (m < 6 ? Wn2 : Wn3)) + (long long)(m % 3) * DIM * DIM;
        __half* dh = g_Wb + (long long)m * DIM * DIM;
        int idx0 = y * 1024;
        #pragma unroll
        for (int i = 0; i < 8; i++) {
            int f = idx0 + i * 128 + tid;
            int k = f >> 7, n = f & 127;
            dh[n * DIM + k] = __float2half_rn(src[f]);
        }
    } else if (b < SB_ZC0) {
        int idx = (b - SB_PR0) * 1024 + tid;
        #pragma unroll
        for (int i = 0; i < 8; i++) {
            int f = idx + i * 128;
            int k = f >> 6, n = f & 63;
            g_Wr[n * 512 + k] = __float2half_rn(Wr1[f]);
        }
    } else if (b < SB_MS0) {
        int i = (b - SB_ZC0) * 128 + tid;
        if (i < N_NODES) g_cnt[i] = 0;
    } else if (b < SB_EMB0) {
        #pragma unroll
        for (int i = 0; i < 4; i++) out[tid + i * 128] = 0.0f;
        g_flag[tid] = 0;
        if (tid < NB_SCAN - 128) g_flag[tid + 128] = 0;
    } else {
        // embed -> fp16 H[:, 0:128]. N*16 groups of 8 floats.
        int i = (b - SB_EMB0) * 128 + tid;
        int n = i >> 4, q = i & 15;
        const float4* e = (const float4*)(emb + (long long)at[n] * DIM) + q * 2;
        float4 v0 = __ldg(e), v1 = __ldg(e + 1);
        __half2 h0 = __floats2half2_rn(v0.x, v0.y);
        __half2 h1 = __floats2half2_rn(v0.z, v0.w);
        __half2 h2 = __floats2half2_rn(v1.x, v1.y);
        __half2 h3 = __floats2half2_rn(v1.z, v1.w);
        uint4 o = make_uint4(*(uint32_t*)&h0, *(uint32_t*)&h1,
                             *(uint32_t*)&h2, *(uint32_t*)&h3);
        *((uint4*)(g_H + (long long)n * 512) + q) = o;
    }
}

// ---------------- CSR: hist + lookback scan + scatter ----------------
__global__ void hist_kernel(const int* __restrict__ dst) {
    int e = blockIdx.x * 256 + threadIdx.x;
    if (e < N_EDGES) atomicAdd(&g_cnt[dst[e]], 1);
}

__global__ void scan_lb() {
    __shared__ int sh[256];
    __shared__ int s_excl;
    int b = blockIdx.x, tid = threadIdx.x;
    int n = b * 256 + tid;
    int v = (n < N_NODES) ? g_cnt[n] : 0;
    sh[tid] = v; __syncthreads();
    #pragma unroll
    for (int o = 1; o < 256; o <<= 1) {
        int t = (tid >= o) ? sh[tid - o] : 0;
        __syncthreads();
        sh[tid] += t;
        __syncthreads();
    }
    if (tid == 0) {
        int total = sh[255];
        if (b == 0) {
            g_inclV[0] = total;
            __threadfence();
            g_flag[0] = 2;
            s_excl = 0;
        } else {
            g_aggrV[b] = total;
            __threadfence();
            g_flag[b] = 1;
            int excl = 0, j = b - 1;
            while (true) {
                int f;
                do { f = g_flag[j]; } while (f == 0);
                if (f == 2) { excl += g_inclV[j]; break; }
                excl += g_aggrV[j];
                j--;
            }
            g_inclV[b] = excl + total;
            __threadfence();
            g_flag[b] = 2;
            s_excl = excl;
        }
    }
    __syncthreads();
    if (n < N_NODES) {
        int o = s_excl + sh[tid] - v;
        g_off[n] = o;
        g_cur[n] = o;
    }
    if (n == 0) g_off[N_NODES] = N_EDGES;
}

__global__ void scatter_kernel(const int* __restrict__ src, const int* __restrict__ dst,
                               const float* __restrict__ dist) {
    int e = blockIdx.x * 256 + threadIdx.x;
    if (e >= N_EDGES) return;
    int d = __ldg(dst + e);
    int pos = atomicAdd(&g_cur[d], 1);
    float di = __ldg(dist + e);
    float t = di * ((float)(GRID_G - 1) / 10.0f);
    int gg = (int)(t + 0.5f);
    gg = gg < GRID_G - 1 ? gg : GRID_G - 1;
    g_recP[pos] = (unsigned)__ldg(src + e) | ((unsigned)gg << 16);
}

// ---------------- edge gather (locked R12 shape) ----------------
__device__ __forceinline__ void eacc(float4& acc, uint2 tv, uint2 hv) {
    float2 t01 = __half22float2(*(__half2*)&tv.x);
    float2 t23 = __half22float2(*(__half2*)&tv.y);
    float2 h01 = __half22float2(*(__half2*)&hv.x);
    float2 h23 = __half22float2(*(__half2*)&hv.y);
    acc.x = fmaf(t01.x, h01.x, acc.x);
    acc.y = fmaf(t01.y, h01.y, acc.y);
    acc.z = fmaf(t23.x, h23.x, acc.z);
    acc.w = fmaf(t23.y, h23.y, acc.w);
}

__global__ __launch_bounds__(256) void edge_gather(
    const __half* __restrict__ tabp,
    const __half* __restrict__ hn,
    __half* __restrict__ node2)
{
    int wid = threadIdx.x >> 5, lane = threadIdx.x & 31;
    int n = blockIdx.x * 8 + wid;
    if (n >= N_NODES) return;
    int beg = __ldg(&g_off[n]);
    int end = __ldg(&g_off[n + 1]);
    float4 acc = make_float4(0.f, 0.f, 0.f, 0.f);
    int i = beg;
    for (; i + 4 <= end; i += 4) {
        unsigned r0 = __ldg(&g_recP[i]);
        unsigned r1 = __ldg(&g_recP[i + 1]);
        unsigned r2 = __ldg(&g_recP[i + 2]);
        unsigned r3 = __ldg(&g_recP[i + 3]);
        uint2 t0 = __ldg((const uint2*)(tabp + (long long)(r0 >> 16) * DIM) + lane);
        uint2 t1 = __ldg((const uint2*)(tabp + (long long)(r1 >> 16) * DIM) + lane);
        uint2 t2 = __ldg((const uint2*)(tabp + (long long)(r2 >> 16) * DIM) + lane);
        uint2 t3 = __ldg((const uint2*)(tabp + (long long)(r3 >> 16) * DIM) + lane);
        uint2 h0 = __ldg((const uint2*)(hn + (long long)(r0 & 0xFFFFu) * DIM) + lane);
        uint2 h1 = __ldg((const uint2*)(hn + (long long)(r1 & 0xFFFFu) * DIM) + lane);
        uint2 h2 = __ldg((const uint2*)(hn + (long long)(r2 & 0xFFFFu) * DIM) + lane);
        uint2 h3 = __ldg((const uint2*)(hn + (long long)(r3 & 0xFFFFu) * DIM) + lane);
        eacc(acc, t0, h0);
        eacc(acc, t1, h1);
        eacc(acc, t2, h2);
        eacc(acc, t3, h3);
    }
    for (; i < end; i++) {
        unsigned r = __ldg(&g_recP[i]);
        uint2 tv = __ldg((const uint2*)(tabp + (long long)(r >> 16) * DIM) + lane);
        uint2 hv = __ldg((const uint2*)(hn + (long long)(r & 0xFFFFu) * DIM) + lane);
        eacc(acc, tv, hv);
    }
    __half2 o01 = __floats2half2_rn(acc.x, acc.y);
    __half2 o23 = __floats2half2_rn(acc.z, acc.w);
    *(uint2*)(node2 + (long long)n * DIM + lane * 4) =
        make_uint2(*(uint32_t*)&o01, *(uint32_t*)&o23);
}

// ---------------- merged: gemm_tab (384 blocks) + gemm_m1 (938 blocks) ----------------
__global__ __launch_bounds__(256) void gemm_tab_m1(
    const float* __restrict__ b_n1, int M)
{
    extern __shared__ uint32_t sm[];
    int tid = threadIdx.x, wid = tid >> 5, lane = tid & 31;
    int mw = wid & 3, nw = wid >> 2;
    int g = lane >> 2, tg = lane & 3;

    if (blockIdx.x < 384) {
        int l = blockIdx.x / 128;
        int r0 = (blockIdx.x % 128) * 64;
        const float* X = g_Spu + (long long)l * GRID_G * DIM;
        __half* Y = g_TabP + (long long)l * GRID_G * DIM;

        load_A_f(sm, X, DIM, 0, r0, GRID_G, tid);
        load_B(sm, g_Wf + (long long)l * DIM * DIM, tid);
        __syncthreads();

        float acc[8][4];
        #pragma unroll
        for (int t = 0; t < 8; t++)
            #pragma unroll
            for (int i = 0; i < 4; i++) acc[t][i] = 0.0f;
        mma_core1<8>(sm, mw, nw * 64, g, tg, acc);

        int row0 = r0 + mw * 16 + g, row1 = row0 + 8;
        #pragma unroll
        for (int t = 0; t < 8; t++) {
            int col = nw * 64 + t * 8 + tg * 2;
            float b0 = g_bf[l * DIM + col], b1 = g_bf[l * DIM + col + 1];
            *(__half2*)(Y + (long long)row0 * DIM + col) =
                __floats2half2_rn(acc[t][0] + b0, acc[t][1] + b1);
            *(__half2*)(Y + (long long)row1 * DIM + col) =
                __floats2half2_rn(acc[t][2] + b0, acc[t][3] + b1);
        }
    } else {
        int r0 = (int)(blockIdx.x - 384) * 64;

        load_A_h(sm, g_H, 512, 0, r0, M, tid);
        load_B(sm, g_Wb, tid);
        __syncthreads();

        float acc[8][4];
        #pragma unroll
        for (int t = 0; t < 8; t++)
            #pragma unroll
            for (int i = 0; i < 4; i++) acc[t][i] = 0.0f;
        mma_core1<8>(sm, mw, nw * 64, g, tg, acc);

        int row0 = r0 + mw * 16 + g, row1 = row0 + 8;
        #pragma unroll
        for (int t = 0; t < 8; t++) {
            int col = nw * 64 + t * 8 + tg * 2;
            float b0 = __ldg(b_n1 + col) + 1.0f;
            float b1 = __ldg(b_n1 + col + 1) + 1.0f;
            if (row0 < M)
                *(__half2*)(g_Hn2 + (long long)row0 * DIM + col) =
                    __floats2half2_rn(acc[t][0] + b0, acc[t][1] + b1);
            if (row1 < M)
                *(__half2*)(g_Hn2 + (long long)row1 * DIM + col) =
                    __floats2half2_rn(acc[t][2] + b0, acc[t][3] + b1);
        }
    }
}

// ---------------- fused: H' = H + sp(Node2@W2+b2)@W3+b3 ; optionally next Hn ----------------
__global__ __launch_bounds__(256) void gemm_m23(
    const __half* __restrict__ X,
    const __half* __restrict__ W2, const float* __restrict__ b2,
    const __half* __restrict__ W3, const float* __restrict__ b3,
    const __half* __restrict__ Res, int sr,
    __half* __restrict__ Y, int sy,
    const __half* __restrict__ W1, const float* __restrict__ b1n,
    __half* __restrict__ Hn2,
    int has_next, int M)
{
    extern __shared__ uint32_t sm[];
    uint32_t* A = sm + OFF_A;
    int tid = threadIdx.x, wid = tid >> 5, lane = tid & 31;
    int mw = wid & 3, nw = wid >> 2;
    int g = lane >> 2, tg = lane & 3;
    int r0 = blockIdx.x * 64;
    int rl0 = mw * 16 + g, rl1 = rl0 + 8;
    int row0 = r0 + rl0, row1 = row0 + 8;

    load_A_h(sm, X, DIM, 0, r0, M, tid);
    load_B(sm, W2, tid);
    __syncthreads();

    float acc[8][4];
    #pragma unroll
    for (int t = 0; t < 8; t++)
        #pragma unroll
        for (int i = 0; i < 4; i++) acc[t][i] = 0.0f;
    mma_core1<8>(sm, mw, nw * 64, g, tg, acc);

    #pragma unroll
    for (int t = 0; t < 8; t++) {
        int col = nw * 64 + t * 8 + tg * 2;
        float b0 = __ldg(b2 + col), b1 = __ldg(b2 + col + 1);
        __half2 v0 = __floats2half2_rn(sp_half(acc[t][0] + b0), sp_half(acc[t][1] + b1));
        __half2 v1 = __floats2half2_rn(sp_half(acc[t][2] + b0), sp_half(acc[t][3] + b1));
        A[rl0 * ASTR + (col >> 1)] = *(uint32_t*)&v0;
        A[rl1 * ASTR + (col >> 1)] = *(uint32_t*)&v1;
    }
    __syncthreads();
    load_B(sm, W3, tid);
    __syncthreads();

    #pragma unroll
    for (int t = 0; t < 8; t++)
        #pragma unroll
        for (int i = 0; i < 4; i++) acc[t][i] = 0.0f;
    mma_core1<8>(sm, mw, nw * 64, g, tg, acc);

    #pragma unroll
    for (int t = 0; t < 8; t++) {
        int col = nw * 64 + t * 8 + tg * 2;
        float b0 = __ldg(b3 + col), b1 = __ldg(b3 + col + 1);
        float y0 = acc[t][0] + b0, y1 = acc[t][1] + b1;
        float y2 = acc[t][2] + b0, y3 = acc[t][3] + b1;
        if (row0 < M) {
            float2 rf = __half22float2(*(const __half2*)(Res + (long long)row0 * sr + col));
            y0 += rf.x; y1 += rf.y;
            __half2 v0 = __floats2half2_rn(y0, y1);
            *(__half2*)(Y + (long long)row0 * sy + col) = v0;
            if (has_next) A[rl0 * ASTR + (col >> 1)] = *(uint32_t*)&v0;
        }
        if (row1 < M) {
            float2 rf = __half22float2(*(const __half2*)(Res + (long long)row1 * sr + col));
            y2 += rf.x; y3 += rf.y;
            __half2 v1 = __floats2half2_rn(y2, y3);
            *(__half2*)(Y + (long long)row1 * sy + col) = v1;
            if (has_next) A[rl1 * ASTR + (col >> 1)] = *(uint32_t*)&v1;
        }
    }
    if (!has_next) return;

    __syncthreads();
    load_B(sm, W1, tid);
    __syncthreads();

    #pragma unroll
    for (int t = 0; t < 8; t++)
        #pragma unroll
        for (int i = 0; i < 4; i++) acc[t][i] = 0.0f;
    mma_core1<8>(sm, mw, nw * 64, g, tg, acc);

    #pragma unroll
    for (int t = 0; t < 8; t++) {
        int col = nw * 64 + t * 8 + tg * 2;
        float b0 = __ldg(b1n + col) + 1.0f;
        float b1 = __ldg(b1n + col + 1) + 1.0f;
        if (row0 < M)
            *(__half2*)(Hn2 + (long long)row0 * DIM + col) =
                __floats2half2_rn(acc[t][0] + b0, acc[t][1] + b1);
        if (row1 < M)
            *(__half2*)(Hn2 + (long long)row1 * DIM + col) =
                __floats2half2_rn(acc[t][2] + b0, acc[t][3] + b1);
    }
}

// ---------------- fused readout ----------------
__global__ __launch_bounds__(256) void gemm_r(
    const __half* __restrict__ X,
    const __half* __restrict__ W,
    const float* __restrict__ br1, const float* __restrict__ Wr2,
    const float* __restrict__ br2,
    const int* __restrict__ gid, float* __restrict__ out, int M)
{
    extern __shared__ uint32_t sm[];
    __shared__ float res[64];
    int tid = threadIdx.x, wid = tid >> 5, lane = tid & 31;
    int mw = wid & 3, nw = wid >> 2;
    int g = lane >> 2, tg = lane & 3;
    int r0 = blockIdx.x * 64;
    if (tid < 64) res[tid] = 0.0f;

    float acc[4][4];
    #pragma unroll
    for (int t = 0; t < 4; t++)
        #pragma unroll
        for (int i = 0; i < 4; i++) acc[t][i] = 0.0f;

    for (int ch = 0; ch < 4; ch++) {
        load_A_h(sm, X, 512, ch * 128, r0, M, tid);
        load_B_r(sm, W, ch, tid);
        __syncthreads();
        mma_core1<4>(sm, mw, nw * 32, g, tg, acc);
        __syncthreads();
    }

    float p0 = 0.0f, p1 = 0.0f;
    #pragma unroll
    for (int t = 0; t < 4; t++) {
        int col = nw * 32 + t * 8 + tg * 2;
        float b0 = __ldg(br1 + col), b1 = __ldg(br1 + col + 1);
        float w0 = __ldg(Wr2 + col), w1 = __ldg(Wr2 + col + 1);
        p0 += sp_one(acc[t][0] + b0) * w0 + sp_one(acc[t][1] + b1) * w1;
        p1 += sp_one(acc[t][2] + b0) * w0 + sp_one(acc[t][3] + b1) * w1;
    }
    p0 += __shfl_down_sync(0xffffffff, p0, 1);
    p0 += __shfl_down_sync(0xffffffff, p0, 2);
    p1 += __shfl_down_sync(0xffffffff, p1, 1);
    p1 += __shfl_down_sync(0xffffffff, p1, 2);
    if (tg == 0) {
        atomicAdd(&res[mw * 16 + g], p0);
        atomicAdd(&res[mw * 16 + g + 8], p1);
    }
    __syncthreads();
    if (tid < 64) {
        int row = r0 + tid;
        if (row < M) atomicAdd(out + __ldg(gid + row), res[tid] + __ldg(br2));
    }
}

// ---------------- launch ----------------
extern "C" void kernel_launch(void* const* d_in, const int* in_sizes, int n_in,
                              void* d_out, int out_size) {
    const int*   atom_type = (const int*)d_in[0];
    const int*   src  = (const int*)d_in[1];
    const int*   dst  = (const int*)d_in[2];
    const int*   gid  = (const int*)d_in[3];
    const float* dist = (const float*)d_in[4];
    const float* emb  = (const float*)d_in[5];
    const float* W_n1 = (const float*)d_in[6];  const float* b_n1 = (const float*)d_in[7];
    const float* W_c1 = (const float*)d_in[8];  const float* b_c1 = (const float*)d_in[9];
    const float* W_c2 = (const float*)d_in[10]; const float* b_c2 = (const float*)d_in[11];
    const float* W_c3 = (const float*)d_in[12]; const float* b_c3 = (const float*)d_in[13];
    const float* W_n2 = (const float*)d_in[14]; const float* b_n2 = (const float*)d_in[15];
    const float* W_n3 = (const float*)d_in[16]; const float* b_n3 = (const float*)d_in[17];
    const float* W_r1 = (const float*)d_in[18]; const float* b_r1 = (const float*)d_in[19];
    const float* W_r2 = (const float*)d_in[20]; const float* b_r2 = (const float*)d_in[21];
    float* out = (float*)d_out;

    __half *H, *Hn2, *Node2, *TabP, *Wb, *Wr;
    cudaGetSymbolAddress((void**)&H,     g_H);
    cudaGetSymbolAddress((void**)&Hn2,   g_Hn2);
    cudaGetSymbolAddress((void**)&Node2, g_Node2);
    cudaGetSymbolAddress((void**)&TabP,  g_TabP);
    cudaGetSymbolAddress((void**)&Wb,    g_Wb);
    cudaGetSymbolAddress((void**)&Wr,    g_Wr);

    cudaFuncSetAttribute(gemm_tab_m1, cudaFuncAttributeMaxDynamicSharedMemorySize, TSMEM_M);
    cudaFuncSetAttribute(gemm_m23,    cudaFuncAttributeMaxDynamicSharedMemorySize, TSMEM_M);
    cudaFuncSetAttribute(gemm_r,      cudaFuncAttributeMaxDynamicSharedMemorySize, TSMEM_R);

    const int M = N_NODES;
    const int GB64 = (M + 63) / 64;     // 938
    const int EB = (N_EDGES + 255) / 256;

    setup1<<<SB_TOTAL, 128>>>(W_c2, b_c2, W_c3, b_c3, W_c1, b_c1,
                              W_n1, W_n2, W_n3, W_r1, atom_type, emb, out);
    hist_kernel<<<EB, 256>>>(dst);
    scan_lb<<<NB_SCAN, 256>>>();
    scatter_kernel<<<EB, 256>>>(src, dst, dist);
    gemm_tab_m1<<<384 + GB64, 256, TSMEM_M>>>(b_n1, M);

    for (int l = 0; l < N_LAYERS; l++) {
        edge_gather<<<(N_NODES + 7) / 8, 256>>>(
            TabP + (long long)l * GRID_G * DIM, Hn2, Node2);
        int nl = l + 1;
        int has_next = (nl < N_LAYERS);
        gemm_m23<<<GB64, 256, TSMEM_M>>>(
            Node2,
            Wb + (long long)(3 + l) * DIM * DIM, b_n2 + l * 128,
            Wb + (long long)(6 + l) * DIM * DIM, b_n3 + l * 128,
            H + l * 128, 512, H + nl * 128, 512,
            Wb + (long long)(has_next ? nl : 0) * DIM * DIM,
            b_n1 + (has_next ? nl : 0) * 128,
            Hn2, has_next, M);
    }

    gemm_r<<<GB64, 256, TSMEM_R>>>(H, Wr, b_r1, W_r2, b_r2, gid, out, M);
}